// round 1
// baseline (speedup 1.0000x reference)
#include <cuda_runtime.h>
#include <cuda_bf16.h>
#include <math.h>

#define Bn 8
#define Cc 32
#define Hh 256
#define Ww 256
#define HW (Hh*Ww)

// Scratch buffers (allocation-free rule: __device__ globals)
__device__ float g_bufA[Bn*Cc*HW];     //  67 MB: conv outputs (32 ch)
__device__ float g_bufB[Bn*4*Cc*HW];   // 268 MB: IRNN outputs (128 ch)

// ---------------------------------------------------------------------------
// Direct 3x3 conv, pad=1, Cout=32. Block = 256 threads (16x16 logical).
// Each thread: 4 consecutive x-pixels, 8 output channels (one co-group).
// Grid: (W/64, H/16, B*4)  z = b*4 + cog
// ---------------------------------------------------------------------------
template<int CIN, bool RELU>
__global__ void __launch_bounds__(256) conv3x3_kernel(
    const float* __restrict__ in, const float* __restrict__ wgt,
    float* __restrict__ outp)
{
    __shared__ float s_in[18*68];
    __shared__ float s_w[72];

    const int tid = threadIdx.x;
    const int tx  = tid & 15;        // 0..15 -> 4 pixels each => 64 wide
    const int ty  = tid >> 4;        // 0..15
    const int x0  = blockIdx.x * 64;
    const int y0  = blockIdx.y * 16;
    const int b   = blockIdx.z >> 2;
    const int cog = blockIdx.z & 3;  // co group: channels cog*8..cog*8+7

    float acc[8][4];
#pragma unroll
    for (int i = 0; i < 8; i++)
#pragma unroll
        for (int j = 0; j < 4; j++) acc[i][j] = 0.f;

    for (int ci = 0; ci < CIN; ci++) {
        // stage input tile (66 x 18 valid, stride 68) for channel ci
        const float* gin = in + (size_t)(b*CIN + ci) * HW;
        for (int idx = tid; idx < 18*66; idx += 256) {
            int r  = idx / 66, cc = idx % 66;
            int gy = y0 - 1 + r, gx = x0 - 1 + cc;
            float v = 0.f;
            if (gy >= 0 && gy < Hh && gx >= 0 && gx < Ww) v = gin[gy*Ww + gx];
            s_in[r*68 + cc] = v;
        }
        // stage 8x9 weights for this ci
        if (tid < 72) {
            int co = tid / 9, k = tid % 9;
            s_w[tid] = wgt[((cog*8 + co)*CIN + ci)*9 + k];
        }
        __syncthreads();

        // 3x6 input window in registers (covers 4 output pixels)
        float v[3][6];
#pragma unroll
        for (int dy = 0; dy < 3; dy++)
#pragma unroll
            for (int dx = 0; dx < 6; dx++)
                v[dy][dx] = s_in[(ty + dy)*68 + tx*4 + dx];

#pragma unroll
        for (int co = 0; co < 8; co++) {
            float wr[9];
#pragma unroll
            for (int k = 0; k < 9; k++) wr[k] = s_w[co*9 + k];
#pragma unroll
            for (int p = 0; p < 4; p++) {
                float s = acc[co][p];
#pragma unroll
                for (int dy = 0; dy < 3; dy++)
#pragma unroll
                    for (int dx = 0; dx < 3; dx++)
                        s = fmaf(wr[dy*3 + dx], v[dy][dx + p], s);
                acc[co][p] = s;
            }
        }
        __syncthreads();
    }

#pragma unroll
    for (int co = 0; co < 8; co++) {
        int o = cog*8 + co;
        float* gout = outp + (size_t)(b*32 + o)*HW + (y0 + ty)*Ww + x0 + tx*4;
        float4 r;
        r.x = acc[co][0]; r.y = acc[co][1]; r.z = acc[co][2]; r.w = acc[co][3];
        if (RELU) {
            r.x = fmaxf(r.x, 0.f); r.y = fmaxf(r.y, 0.f);
            r.z = fmaxf(r.z, 0.f); r.w = fmaxf(r.w, 0.f);
        }
        *reinterpret_cast<float4*>(gout) = r;
    }
}

// ---------------------------------------------------------------------------
// H-direction scans (up = dir0, down = dir2). Thread per (b,c,w) column.
// in: 32-ch tensor, out: 128-ch tensor (concat [up,right,down,left])
// ---------------------------------------------------------------------------
__global__ void __launch_bounds__(256) hscan_kernel(
    const float* __restrict__ in, float* __restrict__ outp,
    const float* __restrict__ wp, const float* __restrict__ bp)
{
    int tid = blockIdx.x * blockDim.x + threadIdx.x;   // B*C*W threads
    int w = tid & (Ww - 1);
    int c = (tid >> 8) & (Cc - 1);
    int b = tid >> 13;

    const float* gin = in + (size_t)(b*Cc + c)*HW + w;
    float* gu = outp + (size_t)(b*4*Cc + 0*Cc + c)*HW + w;   // up
    float* gd = outp + (size_t)(b*4*Cc + 2*Cc + c)*HW + w;   // down

    // down: rows 0..H-1, row 0 raw
    {
        float wc = wp[2*Cc + c], bc = bp[2*Cc + c];
        float h = gin[0];
        gd[0] = h;
#pragma unroll 4
        for (int i = 1; i < Hh; i++) {
            float x = gin[i*Ww];
            h = fmaxf(fmaf(wc, h, x + bc), 0.f);
            gd[i*Ww] = h;
        }
    }
    // up: rows H-1..0, row H-1 raw
    {
        float wc = wp[0*Cc + c], bc = bp[0*Cc + c];
        float h = gin[(Hh-1)*Ww];
        gu[(Hh-1)*Ww] = h;
#pragma unroll 4
        for (int i = Hh - 2; i >= 0; i--) {
            float x = gin[i*Ww];
            h = fmaxf(fmaf(wc, h, x + bc), 0.f);
            gu[i*Ww] = h;
        }
    }
}

// ---------------------------------------------------------------------------
// W-direction scans (right = dir1, left = dir3). Block handles 16 rows of one
// (b,c) plane via smem tile (stride 257 -> conflict-free column walk).
// ---------------------------------------------------------------------------
__global__ void __launch_bounds__(128) wscan_kernel(
    const float* __restrict__ in, float* __restrict__ outp,
    const float* __restrict__ wp, const float* __restrict__ bp)
{
    __shared__ float xs[16*257];
    __shared__ float ys[16*257];

    const int tid = threadIdx.x;
    int blk = blockIdx.x;              // b*C*16 + c*16 + rowTile
    int rt = blk & 15;
    int c  = (blk >> 4) & (Cc - 1);
    int b  = blk >> 9;

    const float* gin = in + (size_t)(b*Cc + c)*HW + rt*16*Ww;
    float* gr = outp + (size_t)(b*4*Cc + 1*Cc + c)*HW + rt*16*Ww;  // right
    float* gl = outp + (size_t)(b*4*Cc + 3*Cc + c)*HW + rt*16*Ww;  // left

    // load tile coalesced
    for (int i = tid; i < 16*256; i += 128) {
        int r = i >> 8, cc = i & 255;
        xs[r*257 + cc] = gin[r*Ww + cc];
    }
    __syncthreads();

    // right scan (col 0 raw)
    if (tid < 16) {
        float wc = wp[1*Cc + c], bc = bp[1*Cc + c];
        float* xr = xs + tid*257;
        float* yr = ys + tid*257;
        float h = xr[0];
        yr[0] = h;
#pragma unroll 8
        for (int cc = 1; cc < Ww; cc++) {
            h = fmaxf(fmaf(wc, h, xr[cc] + bc), 0.f);
            yr[cc] = h;
        }
    }
    __syncthreads();
    for (int i = tid; i < 16*256; i += 128) {
        int r = i >> 8, cc = i & 255;
        gr[r*Ww + cc] = ys[r*257 + cc];
    }
    __syncthreads();

    // left scan (col W-1 raw)
    if (tid < 16) {
        float wc = wp[3*Cc + c], bc = bp[3*Cc + c];
        float* xr = xs + tid*257;
        float* yr = ys + tid*257;
        float h = xr[Ww-1];
        yr[Ww-1] = h;
#pragma unroll 8
        for (int cc = Ww - 2; cc >= 0; cc--) {
            h = fmaxf(fmaf(wc, h, xr[cc] + bc), 0.f);
            yr[cc] = h;
        }
    }
    __syncthreads();
    for (int i = tid; i < 16*256; i += 128) {
        int r = i >> 8, cc = i & 255;
        gl[r*Ww + cc] = ys[r*257 + cc];
    }
}

// ---------------------------------------------------------------------------
// 1x1 conv (32 -> 1) + sigmoid
// ---------------------------------------------------------------------------
__global__ void __launch_bounds__(256) convout_kernel(
    const float* __restrict__ in, const float* __restrict__ wgt,
    float* __restrict__ outp)
{
    int tid = blockIdx.x * blockDim.x + threadIdx.x;   // B*HW
    int p = tid & (HW - 1);
    int b = tid >> 16;
    const float* gin = in + (size_t)b*Cc*HW + p;
    float s = 0.f;
#pragma unroll
    for (int c = 0; c < Cc; c++) s = fmaf(wgt[c], gin[c*HW], s);
    outp[tid] = 1.f / (1.f + expf(-s));
}

// ---------------------------------------------------------------------------
extern "C" void kernel_launch(void* const* d_in, const int* in_sizes, int n_in,
                              void* d_out, int out_size)
{
    const float* x     = (const float*)d_in[0];
    const float* w_in  = (const float*)d_in[1];
    const float* w2    = (const float*)d_in[2];
    const float* w3    = (const float*)d_in[3];
    const float* w_out = (const float*)d_in[4];
    const float* i1w   = (const float*)d_in[5];
    const float* i1b   = (const float*)d_in[6];
    const float* i2w   = (const float*)d_in[7];
    const float* i2b   = (const float*)d_in[8];
    float* out = (float*)d_out;

    float *dA = nullptr, *dB = nullptr;
    cudaGetSymbolAddress((void**)&dA, g_bufA);
    cudaGetSymbolAddress((void**)&dB, g_bufB);

    dim3 cgrid(Ww/64, Hh/16, Bn*4);

    // 1. conv_in: x -> bufA
    conv3x3_kernel<32, false><<<cgrid, 256>>>(x, w_in, dA);
    // 2. irnn1: bufA -> bufB
    hscan_kernel<<<(Bn*Cc*Ww)/256, 256>>>(dA, dB, i1w, i1b);
    wscan_kernel<<<Bn*Cc*16, 128>>>(dA, dB, i1w, i1b);
    // 3. conv2: bufB -> bufA
    conv3x3_kernel<128, false><<<cgrid, 256>>>(dB, w2, dA);
    // 4. irnn2: bufA -> bufB
    hscan_kernel<<<(Bn*Cc*Ww)/256, 256>>>(dA, dB, i2w, i2b);
    wscan_kernel<<<Bn*Cc*16, 128>>>(dA, dB, i2w, i2b);
    // 5. conv3 + relu: bufB -> bufA
    conv3x3_kernel<128, true><<<cgrid, 256>>>(dB, w3, dA);
    // 6. conv_out + sigmoid: bufA -> d_out
    convout_kernel<<<(Bn*HW)/256, 256>>>(dA, w_out, out);
}

// round 3
// speedup vs baseline: 3.7171x; 3.7171x over previous
#include <cuda_runtime.h>
#include <cuda_bf16.h>
#include <math.h>
#include <stdint.h>

#define Bn 8
#define Cc 32
#define Hh 256
#define Ww 256
#define HW (Hh*Ww)

// ---------------------------------------------------------------------------
// Scratch buffers (allocation-free rule: __device__ globals)
// ---------------------------------------------------------------------------
__device__ __align__(16) float g_bufA[Bn*Cc*HW];     //  67 MB: conv outputs (32 ch)
__device__ __align__(16) float g_bufB[Bn*4*Cc*HW];   // 268 MB: IRNN outputs (128 ch)
// tf32-converted, padded weight images: [tap(9)][co(32)][ci + 4 pad]
__device__ __align__(16) float g_win_cv[9*32*(32+4)];    // CIN=32
__device__ __align__(16) float g_w2_cv[9*32*(128+4)];    // CIN=128
__device__ __align__(16) float g_w3_cv[9*32*(128+4)];

__device__ __forceinline__ uint32_t f2tf32(float f) {
    uint32_t t;
    asm("cvt.rna.tf32.f32 %0, %1;" : "=r"(t) : "f"(f));
    return t;
}

// ---------------------------------------------------------------------------
// Weight prep: OIHW fp32 -> [tap][co][ci] tf32 with ci padded to CIN+4.
// ---------------------------------------------------------------------------
template<int CIN>
__global__ void prep_w_kernel(const float* __restrict__ w, float* __restrict__ wbuf)
{
    int idx = blockIdx.x * 256 + threadIdx.x;
    if (idx >= 32*CIN*9) return;
    int dx = idx % 3;
    int dy = (idx / 3) % 3;
    int ci = (idx / 9) % CIN;
    int co = idx / (9*CIN);
    ((uint32_t*)wbuf)[((dy*3 + dx)*32 + co)*(CIN + 4) + ci] = f2tf32(w[idx]);
}

// ---------------------------------------------------------------------------
// tf32 mma.sync implicit-GEMM 3x3 conv, pad=1, Cout=32.
// CTA: 256 threads, tile 64x4 = 256 pixels. Warp w: pixels [w*32, w*32+32),
// 2 m-blocks x 4 n-blocks of m16n8k8. K = CIN per tap, taps looped.
// smem: weights [9][32][CIN+4] + 2 input chunk buffers [6][66][12] (8ci+4pad).
// ---------------------------------------------------------------------------
template<int CIN, bool RELU>
__global__ void __launch_bounds__(256, 1) conv_mma_kernel(
    const float* __restrict__ in, const float* __restrict__ wbuf,
    float* __restrict__ outp)
{
    constexpr int WPAD = CIN + 4;
    constexpr int WWORDS = 9*32*WPAD;
    constexpr int NCH = CIN/8;
    constexpr int BUFW = 6*66*12;          // 4752 words per chunk buffer
    extern __shared__ float sm[];
    float* wsm = sm;
    float* abufs[2] = { sm + WWORDS, sm + WWORDS + BUFW };

    const int tid = threadIdx.x;
    const int lane = tid & 31;
    const int wrp = tid >> 5;
    const int r4 = lane >> 2;     // 0..7
    const int c4 = lane & 3;      // 0..3

    // stage weights (already converted + padded; straight float4 copy)
    {
        const float4* src = (const float4*)wbuf;
        float4* dst = (float4*)wsm;
        for (int i = tid; i < WWORDS/4; i += 256) dst[i] = src[i];
    }

    for (int tg = blockIdx.x; tg < 2048; tg += gridDim.x) {
        const int b  = tg >> 8;
        const int ty = (tg >> 2) & 63;
        const int tx = tg & 3;
        const int x0 = tx*64, y0 = ty*4;

        float stg[13];

        auto LOADC = [&](int chunk) {
            const float* base = in + (size_t)(b*CIN + chunk*8)*HW;
#pragma unroll
            for (int j = 0; j < 13; j++) {
                int i = tid + j*256;
                float v = 0.f;
                if (i < 3168) {
                    int cio = i / 396;
                    int p = i - cio*396;
                    int iy = p / 66, ix = p - iy*66;
                    int gy = y0 + iy - 1, gx = x0 + ix - 1;
                    if ((unsigned)gy < 256u && (unsigned)gx < 256u)
                        v = __ldg(base + (size_t)cio*HW + gy*256 + gx);
                }
                stg[j] = v;
            }
        };
        auto STOREC = [&](float* dstb) {
            uint32_t* d = (uint32_t*)dstb;
#pragma unroll
            for (int j = 0; j < 13; j++) {
                int i = tid + j*256;
                if (i < 3168) {
                    int cio = i / 396;
                    int p = i - cio*396;
                    d[p*12 + cio] = f2tf32(stg[j]);
                }
            }
        };

        float acc[2][4][4];
#pragma unroll
        for (int mb = 0; mb < 2; mb++)
#pragma unroll
            for (int nb = 0; nb < 4; nb++)
#pragma unroll
                for (int q = 0; q < 4; q++) acc[mb][nb][q] = 0.f;

        LOADC(0);
        STOREC(abufs[0]);

        for (int ch = 0; ch < NCH; ch++) {
            __syncthreads();                    // chunk buffer ready for mma
            if (ch + 1 < NCH) LOADC(ch + 1);    // overlap LDG with mma below

            const uint32_t* bufI = (const uint32_t*)abufs[ch & 1];
            const uint32_t* bw = (const uint32_t*)wsm;
            const int kk = ch*8 + c4;

#pragma unroll
            for (int dy = 0; dy < 3; dy++) {
#pragma unroll
                for (int dx = 0; dx < 3; dx++) {
                    const int tap = dy*3 + dx;
                    uint32_t a[2][4];
#pragma unroll
                    for (int mb = 0; mb < 2; mb++) {
                        int p0 = wrp*32 + mb*16;
                        int py = p0 >> 6, px0 = p0 & 63;
                        int base = ((py + dy)*66 + px0 + dx + r4)*12;
                        a[mb][0] = bufI[base + c4];
                        a[mb][1] = bufI[base + 96 + c4];      // +8 pixels
                        a[mb][2] = bufI[base + c4 + 4];
                        a[mb][3] = bufI[base + 96 + c4 + 4];
                    }
#pragma unroll
                    for (int nb = 0; nb < 4; nb++) {
                        const uint32_t* bp = bw + (tap*32 + nb*8 + r4)*WPAD + kk;
                        uint32_t b0 = bp[0], b1 = bp[4];
#pragma unroll
                        for (int mb = 0; mb < 2; mb++) {
                            asm("mma.sync.aligned.m16n8k8.row.col.f32.tf32.tf32.f32 "
                                "{%0,%1,%2,%3}, {%4,%5,%6,%7}, {%8,%9}, {%0,%1,%2,%3};"
                                : "+f"(acc[mb][nb][0]), "+f"(acc[mb][nb][1]),
                                  "+f"(acc[mb][nb][2]), "+f"(acc[mb][nb][3])
                                : "r"(a[mb][0]), "r"(a[mb][1]),
                                  "r"(a[mb][2]), "r"(a[mb][3]),
                                  "r"(b0), "r"(b1));
                        }
                    }
                }
            }
            if (ch + 1 < NCH) STOREC(abufs[(ch + 1) & 1]);
        }

        // readout: c0=(p,co) c1=(p,co+1) c2=(p+8,co) c3=(p+8,co+1)
#pragma unroll
        for (int mb = 0; mb < 2; mb++) {
            int p = wrp*32 + mb*16 + r4;
            int py = p >> 6, px = p & 63;
            float* orow = outp + (size_t)b*32*HW + (y0 + py)*256 + x0 + px;
#pragma unroll
            for (int nb = 0; nb < 4; nb++) {
                int co = nb*8 + c4*2;
                float v0 = acc[mb][nb][0], v1 = acc[mb][nb][1];
                float v2 = acc[mb][nb][2], v3 = acc[mb][nb][3];
                if (RELU) {
                    v0 = fmaxf(v0, 0.f); v1 = fmaxf(v1, 0.f);
                    v2 = fmaxf(v2, 0.f); v3 = fmaxf(v3, 0.f);
                }
                orow[(size_t)co*HW]           = v0;
                orow[(size_t)(co + 1)*HW]     = v1;
                orow[(size_t)co*HW + 8]       = v2;     // p+8 = same row, px+8
                orow[(size_t)(co + 1)*HW + 8] = v3;
            }
        }
    }
}

// ---------------------------------------------------------------------------
// H-direction scans (up = dir0, down = dir2). Thread per (b,c,w) column.
// ---------------------------------------------------------------------------
__global__ void __launch_bounds__(256) hscan_kernel(
    const float* __restrict__ in, float* __restrict__ outp,
    const float* __restrict__ wp, const float* __restrict__ bp)
{
    int tid = blockIdx.x * blockDim.x + threadIdx.x;
    int w = tid & (Ww - 1);
    int c = (tid >> 8) & (Cc - 1);
    int b = tid >> 13;

    const float* gin = in + (size_t)(b*Cc + c)*HW + w;
    float* gu = outp + (size_t)(b*4*Cc + 0*Cc + c)*HW + w;
    float* gd = outp + (size_t)(b*4*Cc + 2*Cc + c)*HW + w;

    {
        float wc = wp[2*Cc + c], bc = bp[2*Cc + c];
        float h = gin[0];
        gd[0] = h;
#pragma unroll 4
        for (int i = 1; i < Hh; i++) {
            float x = gin[i*Ww];
            h = fmaxf(fmaf(wc, h, x + bc), 0.f);
            gd[i*Ww] = h;
        }
    }
    {
        float wc = wp[0*Cc + c], bc = bp[0*Cc + c];
        float h = gin[(Hh-1)*Ww];
        gu[(Hh-1)*Ww] = h;
#pragma unroll 4
        for (int i = Hh - 2; i >= 0; i--) {
            float x = gin[i*Ww];
            h = fmaxf(fmaf(wc, h, x + bc), 0.f);
            gu[i*Ww] = h;
        }
    }
}

// ---------------------------------------------------------------------------
// W-direction scans (right = dir1, left = dir3) via smem transpose tile.
// ---------------------------------------------------------------------------
__global__ void __launch_bounds__(128) wscan_kernel(
    const float* __restrict__ in, float* __restrict__ outp,
    const float* __restrict__ wp, const float* __restrict__ bp)
{
    __shared__ float xs[16*257];
    __shared__ float ys[16*257];

    const int tid = threadIdx.x;
    int blk = blockIdx.x;
    int rt = blk & 15;
    int c  = (blk >> 4) & (Cc - 1);
    int b  = blk >> 9;

    const float* gin = in + (size_t)(b*Cc + c)*HW + rt*16*Ww;
    float* gr = outp + (size_t)(b*4*Cc + 1*Cc + c)*HW + rt*16*Ww;
    float* gl = outp + (size_t)(b*4*Cc + 3*Cc + c)*HW + rt*16*Ww;

    for (int i = tid; i < 16*256; i += 128) {
        int r = i >> 8, cc = i & 255;
        xs[r*257 + cc] = gin[r*Ww + cc];
    }
    __syncthreads();

    if (tid < 16) {
        float wc = wp[1*Cc + c], bc = bp[1*Cc + c];
        float* xr = xs + tid*257;
        float* yr = ys + tid*257;
        float h = xr[0];
        yr[0] = h;
#pragma unroll 8
        for (int cc = 1; cc < Ww; cc++) {
            h = fmaxf(fmaf(wc, h, xr[cc] + bc), 0.f);
            yr[cc] = h;
        }
    }
    __syncthreads();
    for (int i = tid; i < 16*256; i += 128) {
        int r = i >> 8, cc = i & 255;
        gr[r*Ww + cc] = ys[r*257 + cc];
    }
    __syncthreads();

    if (tid < 16) {
        float wc = wp[3*Cc + c], bc = bp[3*Cc + c];
        float* xr = xs + tid*257;
        float* yr = ys + tid*257;
        float h = xr[Ww-1];
        yr[Ww-1] = h;
#pragma unroll 8
        for (int cc = Ww - 2; cc >= 0; cc--) {
            h = fmaxf(fmaf(wc, h, xr[cc] + bc), 0.f);
            yr[cc] = h;
        }
    }
    __syncthreads();
    for (int i = tid; i < 16*256; i += 128) {
        int r = i >> 8, cc = i & 255;
        gl[r*Ww + cc] = ys[r*257 + cc];
    }
}

// ---------------------------------------------------------------------------
// 1x1 conv (32 -> 1) + sigmoid
// ---------------------------------------------------------------------------
__global__ void __launch_bounds__(256) convout_kernel(
    const float* __restrict__ in, const float* __restrict__ wgt,
    float* __restrict__ outp)
{
    int tid = blockIdx.x * blockDim.x + threadIdx.x;
    int p = tid & (HW - 1);
    int b = tid >> 16;
    const float* gin = in + (size_t)b*Cc*HW + p;
    float s = 0.f;
#pragma unroll
    for (int c = 0; c < Cc; c++) s = fmaf(wgt[c], gin[c*HW], s);
    outp[tid] = 1.f / (1.f + expf(-s));
}

// ---------------------------------------------------------------------------
extern "C" void kernel_launch(void* const* d_in, const int* in_sizes, int n_in,
                              void* d_out, int out_size)
{
    const float* x     = (const float*)d_in[0];
    const float* w_in  = (const float*)d_in[1];
    const float* w2    = (const float*)d_in[2];
    const float* w3    = (const float*)d_in[3];
    const float* w_out = (const float*)d_in[4];
    const float* i1w   = (const float*)d_in[5];
    const float* i1b   = (const float*)d_in[6];
    const float* i2w   = (const float*)d_in[7];
    const float* i2b   = (const float*)d_in[8];
    float* out = (float*)d_out;

    float *dA, *dB, *dWin, *dW2, *dW3;
    cudaGetSymbolAddress((void**)&dA, g_bufA);
    cudaGetSymbolAddress((void**)&dB, g_bufB);
    cudaGetSymbolAddress((void**)&dWin, g_win_cv);
    cudaGetSymbolAddress((void**)&dW2, g_w2_cv);
    cudaGetSymbolAddress((void**)&dW3, g_w3_cv);

    const int SMEM32  = (9*32*36  + 2*4752) * 4;   //  79488 B
    const int SMEM128 = (9*32*132 + 2*4752) * 4;   // 190080 B
    cudaFuncSetAttribute(conv_mma_kernel<32,false>,
                         cudaFuncAttributeMaxDynamicSharedMemorySize, SMEM32);
    cudaFuncSetAttribute(conv_mma_kernel<128,false>,
                         cudaFuncAttributeMaxDynamicSharedMemorySize, SMEM128);
    cudaFuncSetAttribute(conv_mma_kernel<128,true>,
                         cudaFuncAttributeMaxDynamicSharedMemorySize, SMEM128);

    // weight prep (tf32 convert + pad)
    prep_w_kernel<32> <<<(32*32*9  + 255)/256, 256>>>(w_in, dWin);
    prep_w_kernel<128><<<(32*128*9 + 255)/256, 256>>>(w2, dW2);
    prep_w_kernel<128><<<(32*128*9 + 255)/256, 256>>>(w3, dW3);

    // 1. conv_in: x -> bufA
    conv_mma_kernel<32,false><<<296, 256, SMEM32>>>(x, dWin, dA);
    // 2. irnn1: bufA -> bufB
    hscan_kernel<<<(Bn*Cc*Ww)/256, 256>>>(dA, dB, i1w, i1b);
    wscan_kernel<<<Bn*Cc*16, 128>>>(dA, dB, i1w, i1b);
    // 3. conv2: bufB -> bufA
    conv_mma_kernel<128,false><<<148, 256, SMEM128>>>(dB, dW2, dA);
    // 4. irnn2: bufA -> bufB
    hscan_kernel<<<(Bn*Cc*Ww)/256, 256>>>(dA, dB, i2w, i2b);
    wscan_kernel<<<Bn*Cc*16, 128>>>(dA, dB, i2w, i2b);
    // 5. conv3 + relu: bufB -> bufA
    conv_mma_kernel<128,true><<<148, 256, SMEM128>>>(dB, dW3, dA);
    // 6. conv_out + sigmoid: bufA -> d_out
    convout_kernel<<<(Bn*HW)/256, 256>>>(dA, w_out, out);
}

// round 4
// speedup vs baseline: 5.7319x; 1.5420x over previous
#include <cuda_runtime.h>
#include <cuda_bf16.h>
#include <math.h>
#include <stdint.h>

#define Bn 8
#define Cc 32
#define Hh 256
#define Ww 256
#define HW (Hh*Ww)

// ---------------------------------------------------------------------------
// Scratch buffers (allocation-free rule: __device__ globals)
// ---------------------------------------------------------------------------
__device__ __align__(16) float g_bufA[Bn*Cc*HW];     //  67 MB: conv outputs (32 ch)
__device__ __align__(16) float g_bufB[Bn*4*Cc*HW];   // 268 MB: IRNN outputs (128 ch)
// tf32(rna) weights, chunked+permuted: [ch][tap(9)][co(32)][k'(8)]
__device__ __align__(16) float g_win_cv[4*9*32*8];    // CIN=32  (4 chunks)
__device__ __align__(16) float g_w2_cv[16*9*32*8];    // CIN=128 (16 chunks)
__device__ __align__(16) float g_w3_cv[16*9*32*8];

__device__ __forceinline__ uint32_t f2tf32(float f) {
    uint32_t t;
    asm("cvt.rna.tf32.f32 %0, %1;" : "=r"(t) : "f"(f));
    return t;
}
__device__ __forceinline__ uint32_t smem_u32(const void* p) {
    uint32_t a;
    asm("{ .reg .u64 t; cvta.to.shared.u64 t, %1; cvt.u32.u64 %0, t; }" : "=r"(a) : "l"(p));
    return a;
}
__device__ __forceinline__ void cp16(uint32_t dst, const void* src, bool pred) {
    int sz = pred ? 16 : 0;
    asm volatile("cp.async.cg.shared.global [%0], [%1], 16, %2;"
                 :: "r"(dst), "l"(src), "r"(sz) : "memory");
}
__device__ __forceinline__ void cp_commit() {
    asm volatile("cp.async.commit_group;" ::: "memory");
}
template<int N>
__device__ __forceinline__ void cp_wait() {
    asm volatile("cp.async.wait_group %0;" :: "n"(N) : "memory");
}

// ---------------------------------------------------------------------------
// Weight prep: OIHW fp32 -> [ch][tap][co][k'] tf32(rna), k' = 2*(k&3)+(k>>2)
// so that (k, k+4) are adjacent for one LDS.64 B-fragment load.
// ---------------------------------------------------------------------------
template<int CIN>
__global__ void prep_w_kernel(const float* __restrict__ w, float* __restrict__ wbuf)
{
    int idx = blockIdx.x * 256 + threadIdx.x;
    if (idx >= 32*CIN*9) return;
    int dx = idx % 3;
    int dy = (idx / 3) % 3;
    int ci = (idx / 9) % CIN;
    int co = idx / (9*CIN);
    int ch = ci >> 3, k = ci & 7;
    int kp = 2*(k & 3) + (k >> 2);
    int tap = dy*3 + dx;
    ((uint32_t*)wbuf)[((ch*9 + tap)*32 + co)*8 + kp] = f2tf32(w[idx]);
}

// ---------------------------------------------------------------------------
// tf32 mma.sync implicit-GEMM 3x3 conv, pad=1, Cout=32.
// CTA: 256 thr (8 warps), tile 128x4 = 512 px. Warp w: y=w>>1, x in
// [(w&1)*64, +64) as 4 m-blocks of 16. nb=4 (N=32). K = 8ci per chunk x 9 taps.
// smem: input [2][6y][8ci][136x] (x0-4..x0+131), weights [2][9][32][8].
// cp.async double-buffered staging; per-chunk weight slices.
// ---------------------------------------------------------------------------
template<int CIN, bool RELU>
__global__ void __launch_bounds__(256, 2) conv_mma_kernel(
    const float* __restrict__ in, const float* __restrict__ wbuf,
    float* __restrict__ outp)
{
    constexpr int NCH = CIN/8;
    constexpr int INW = 6*8*136;       // 6528 words per input buffer
    constexpr int WW  = 9*32*8;        // 2304 words per weight slice
    extern __shared__ float sm[];
    float* s_in[2] = { sm, sm + INW };
    float* s_w[2]  = { sm + 2*INW, sm + 2*INW + WW };
    const uint32_t s_in_u[2] = { smem_u32(s_in[0]), smem_u32(s_in[1]) };
    const uint32_t s_w_u[2]  = { smem_u32(s_w[0]),  smem_u32(s_w[1])  };

    const int tid = threadIdx.x;
    const int lane = tid & 31;
    const int wrp = tid >> 5;
    const int r4 = lane >> 2;     // 0..7
    const int c4 = lane & 3;      // 0..3
    const int ywarp = wrp >> 1;          // 0..3
    const int xwarp = (wrp & 1) * 64;    // 0 or 64

    for (int tg = blockIdx.x; tg < 1024; tg += gridDim.x) {
        const int b  = tg >> 7;
        const int ty = (tg >> 1) & 63;
        const int tx = tg & 1;
        const int x0 = tx*128, y0 = ty*4;

        auto STAGE = [&](int ch, int bufi) {
            // input: 1632 float4 tasks
            const float* base = in + (size_t)(b*CIN + ch*8)*HW;
#pragma unroll
            for (int k = 0; k < 7; k++) {
                int t = tid + k*256;
                if (t < 1632) {
                    int iy = t / 272;
                    int r  = t - iy*272;
                    int ci = r / 34;
                    int f4 = r - ci*34;
                    int gy = y0 - 1 + iy;
                    int gxs = x0 - 4 + f4*4;
                    bool pred = ((unsigned)gy < 256u) && ((unsigned)gxs <= 252u);
                    const float* src = base + (size_t)ci*HW
                                     + (pred ? (gy*256 + gxs) : 0);
                    cp16(s_in_u[bufi] + (((iy*8 + ci)*136 + f4*4) << 2), src, pred);
                }
            }
            // weights: 576 float4 tasks
            const float* wsrc = wbuf + (size_t)ch*WW;
#pragma unroll
            for (int k = 0; k < 3; k++) {
                int t = tid + k*256;
                if (t < 576)
                    cp16(s_w_u[bufi] + (t << 4), wsrc + t*4, true);
            }
            cp_commit();
        };

        float acc[4][4][4];
#pragma unroll
        for (int mb = 0; mb < 4; mb++)
#pragma unroll
            for (int nb = 0; nb < 4; nb++)
#pragma unroll
                for (int q = 0; q < 4; q++) acc[mb][nb][q] = 0.f;

        STAGE(0, 0);

        for (int ch = 0; ch < NCH; ch++) {
            __syncthreads();                       // all warps done with buf[(ch-1)&1]
            if (ch + 1 < NCH) {
                STAGE(ch + 1, (ch + 1) & 1);
                cp_wait<1>();                      // stage(ch) complete
            } else {
                cp_wait<0>();
            }
            __syncthreads();                       // buf[ch&1] visible to all

            const uint32_t* bufI = (const uint32_t*)s_in[ch & 1];
            const uint32_t* bw   = (const uint32_t*)s_w[ch & 1];

#pragma unroll
            for (int dy = 0; dy < 3; dy++) {
#pragma unroll
                for (int dx = 0; dx < 3; dx++) {
                    const int tap = dy*3 + dx;
                    uint32_t a[4][4];
#pragma unroll
                    for (int mb = 0; mb < 4; mb++) {
                        int iy = ywarp + dy;
                        int sx = xwarp + mb*16 + r4 + dx + 3;
                        int b0 = (iy*8 + c4)*136 + sx;
                        a[mb][0] = bufI[b0];
                        a[mb][1] = bufI[b0 + 8];
                        a[mb][2] = bufI[b0 + 4*136];
                        a[mb][3] = bufI[b0 + 4*136 + 8];
                    }
#pragma unroll
                    for (int nb = 0; nb < 4; nb++) {
                        uint2 bb = *(const uint2*)&bw[((tap*32 + nb*8 + r4) << 3) + c4*2];
#pragma unroll
                        for (int mb = 0; mb < 4; mb++) {
                            asm("mma.sync.aligned.m16n8k8.row.col.f32.tf32.tf32.f32 "
                                "{%0,%1,%2,%3}, {%4,%5,%6,%7}, {%8,%9}, {%0,%1,%2,%3};"
                                : "+f"(acc[mb][nb][0]), "+f"(acc[mb][nb][1]),
                                  "+f"(acc[mb][nb][2]), "+f"(acc[mb][nb][3])
                                : "r"(a[mb][0]), "r"(a[mb][1]),
                                  "r"(a[mb][2]), "r"(a[mb][3]),
                                  "r"(bb.x), "r"(bb.y));
                        }
                    }
                }
            }
        }

        // store: c0=(p,co) c1=(p,co+1) c2=(p+8,co) c3=(p+8,co+1)
#pragma unroll
        for (int mb = 0; mb < 4; mb++) {
            int px = xwarp + mb*16 + r4;
            float* orow = outp + (size_t)b*32*HW + (y0 + ywarp)*256 + x0 + px;
#pragma unroll
            for (int nb = 0; nb < 4; nb++) {
                int co = nb*8 + c4*2;
                float v0 = acc[mb][nb][0], v1 = acc[mb][nb][1];
                float v2 = acc[mb][nb][2], v3 = acc[mb][nb][3];
                if (RELU) {
                    v0 = fmaxf(v0, 0.f); v1 = fmaxf(v1, 0.f);
                    v2 = fmaxf(v2, 0.f); v3 = fmaxf(v3, 0.f);
                }
                orow[(size_t)co*HW]           = v0;
                orow[(size_t)(co + 1)*HW]     = v1;
                orow[(size_t)co*HW + 8]       = v2;
                orow[(size_t)(co + 1)*HW + 8] = v3;
            }
        }
    }
}

// ---------------------------------------------------------------------------
// H-direction scans (up = dir0, down = dir2). Thread per (b,c,w) column.
// ---------------------------------------------------------------------------
__global__ void __launch_bounds__(256) hscan_kernel(
    const float* __restrict__ in, float* __restrict__ outp,
    const float* __restrict__ wp, const float* __restrict__ bp)
{
    int tid = blockIdx.x * blockDim.x + threadIdx.x;
    int w = tid & (Ww - 1);
    int c = (tid >> 8) & (Cc - 1);
    int b = tid >> 13;

    const float* gin = in + (size_t)(b*Cc + c)*HW + w;
    float* gu = outp + (size_t)(b*4*Cc + 0*Cc + c)*HW + w;
    float* gd = outp + (size_t)(b*4*Cc + 2*Cc + c)*HW + w;

    {
        float wc = wp[2*Cc + c], bc = bp[2*Cc + c];
        float h = gin[0];
        gd[0] = h;
#pragma unroll 4
        for (int i = 1; i < Hh; i++) {
            float x = gin[i*Ww];
            h = fmaxf(fmaf(wc, h, x + bc), 0.f);
            gd[i*Ww] = h;
        }
    }
    {
        float wc = wp[0*Cc + c], bc = bp[0*Cc + c];
        float h = gin[(Hh-1)*Ww];
        gu[(Hh-1)*Ww] = h;
#pragma unroll 4
        for (int i = Hh - 2; i >= 0; i--) {
            float x = gin[i*Ww];
            h = fmaxf(fmaf(wc, h, x + bc), 0.f);
            gu[i*Ww] = h;
        }
    }
}

// ---------------------------------------------------------------------------
// W-direction scans (right = dir1, left = dir3) via smem transpose tile.
// ---------------------------------------------------------------------------
__global__ void __launch_bounds__(128) wscan_kernel(
    const float* __restrict__ in, float* __restrict__ outp,
    const float* __restrict__ wp, const float* __restrict__ bp)
{
    __shared__ float xs[16*257];
    __shared__ float ys[16*257];

    const int tid = threadIdx.x;
    int blk = blockIdx.x;
    int rt = blk & 15;
    int c  = (blk >> 4) & (Cc - 1);
    int b  = blk >> 9;

    const float* gin = in + (size_t)(b*Cc + c)*HW + rt*16*Ww;
    float* gr = outp + (size_t)(b*4*Cc + 1*Cc + c)*HW + rt*16*Ww;
    float* gl = outp + (size_t)(b*4*Cc + 3*Cc + c)*HW + rt*16*Ww;

    for (int i = tid; i < 16*256; i += 128) {
        int r = i >> 8, cc = i & 255;
        xs[r*257 + cc] = gin[r*Ww + cc];
    }
    __syncthreads();

    if (tid < 16) {
        float wc = wp[1*Cc + c], bc = bp[1*Cc + c];
        float* xr = xs + tid*257;
        float* yr = ys + tid*257;
        float h = xr[0];
        yr[0] = h;
#pragma unroll 8
        for (int cc = 1; cc < Ww; cc++) {
            h = fmaxf(fmaf(wc, h, xr[cc] + bc), 0.f);
            yr[cc] = h;
        }
    }
    __syncthreads();
    for (int i = tid; i < 16*256; i += 128) {
        int r = i >> 8, cc = i & 255;
        gr[r*Ww + cc] = ys[r*257 + cc];
    }
    __syncthreads();

    if (tid < 16) {
        float wc = wp[3*Cc + c], bc = bp[3*Cc + c];
        float* xr = xs + tid*257;
        float* yr = ys + tid*257;
        float h = xr[Ww-1];
        yr[Ww-1] = h;
#pragma unroll 8
        for (int cc = Ww - 2; cc >= 0; cc--) {
            h = fmaxf(fmaf(wc, h, xr[cc] + bc), 0.f);
            yr[cc] = h;
        }
    }
    __syncthreads();
    for (int i = tid; i < 16*256; i += 128) {
        int r = i >> 8, cc = i & 255;
        gl[r*Ww + cc] = ys[r*257 + cc];
    }
}

// ---------------------------------------------------------------------------
// 1x1 conv (32 -> 1) + sigmoid
// ---------------------------------------------------------------------------
__global__ void __launch_bounds__(256) convout_kernel(
    const float* __restrict__ in, const float* __restrict__ wgt,
    float* __restrict__ outp)
{
    int tid = blockIdx.x * blockDim.x + threadIdx.x;
    int p = tid & (HW - 1);
    int b = tid >> 16;
    const float* gin = in + (size_t)b*Cc*HW + p;
    float s = 0.f;
#pragma unroll
    for (int c = 0; c < Cc; c++) s = fmaf(wgt[c], gin[c*HW], s);
    outp[tid] = 1.f / (1.f + expf(-s));
}

// ---------------------------------------------------------------------------
extern "C" void kernel_launch(void* const* d_in, const int* in_sizes, int n_in,
                              void* d_out, int out_size)
{
    const float* x     = (const float*)d_in[0];
    const float* w_in  = (const float*)d_in[1];
    const float* w2    = (const float*)d_in[2];
    const float* w3    = (const float*)d_in[3];
    const float* w_out = (const float*)d_in[4];
    const float* i1w   = (const float*)d_in[5];
    const float* i1b   = (const float*)d_in[6];
    const float* i2w   = (const float*)d_in[7];
    const float* i2b   = (const float*)d_in[8];
    float* out = (float*)d_out;

    float *dA, *dB, *dWin, *dW2, *dW3;
    cudaGetSymbolAddress((void**)&dA, g_bufA);
    cudaGetSymbolAddress((void**)&dB, g_bufB);
    cudaGetSymbolAddress((void**)&dWin, g_win_cv);
    cudaGetSymbolAddress((void**)&dW2, g_w2_cv);
    cudaGetSymbolAddress((void**)&dW3, g_w3_cv);

    const int SMEM = (2*6528 + 2*2304) * 4;   // 70656 B
    cudaFuncSetAttribute(conv_mma_kernel<32,false>,
                         cudaFuncAttributeMaxDynamicSharedMemorySize, SMEM);
    cudaFuncSetAttribute(conv_mma_kernel<128,false>,
                         cudaFuncAttributeMaxDynamicSharedMemorySize, SMEM);
    cudaFuncSetAttribute(conv_mma_kernel<128,true>,
                         cudaFuncAttributeMaxDynamicSharedMemorySize, SMEM);

    // weight prep (tf32 rna convert + chunk/permute)
    prep_w_kernel<32> <<<(32*32*9  + 255)/256, 256>>>(w_in, dWin);
    prep_w_kernel<128><<<(32*128*9 + 255)/256, 256>>>(w2, dW2);
    prep_w_kernel<128><<<(32*128*9 + 255)/256, 256>>>(w3, dW3);

    // 1. conv_in: x -> bufA
    conv_mma_kernel<32,false><<<296, 256, SMEM>>>(x, dWin, dA);
    // 2. irnn1: bufA -> bufB
    hscan_kernel<<<(Bn*Cc*Ww)/256, 256>>>(dA, dB, i1w, i1b);
    wscan_kernel<<<Bn*Cc*16, 128>>>(dA, dB, i1w, i1b);
    // 3. conv2: bufB -> bufA
    conv_mma_kernel<128,false><<<296, 256, SMEM>>>(dB, dW2, dA);
    // 4. irnn2: bufA -> bufB
    hscan_kernel<<<(Bn*Cc*Ww)/256, 256>>>(dA, dB, i2w, i2b);
    wscan_kernel<<<Bn*Cc*16, 128>>>(dA, dB, i2w, i2b);
    // 5. conv3 + relu: bufB -> bufA
    conv_mma_kernel<128,true><<<296, 256, SMEM>>>(dB, dW3, dA);
    // 6. conv_out + sigmoid: bufA -> d_out
    convout_kernel<<<(Bn*HW)/256, 256>>>(dA, w_out, out);
}

// round 7
// speedup vs baseline: 6.5655x; 1.1454x over previous
#include <cuda_runtime.h>
#include <cuda_bf16.h>
#include <math.h>
#include <stdint.h>

#define Bn 8
#define Cc 32
#define Hh 256
#define Ww 256
#define HW (Hh*Ww)

// ---------------------------------------------------------------------------
// Scratch buffers (allocation-free rule: __device__ globals)
// ---------------------------------------------------------------------------
__device__ __align__(16) float g_bufA[Bn*Cc*HW];     //  67 MB: conv outputs (32 ch)
__device__ __align__(16) float g_bufB[Bn*4*Cc*HW];   // 268 MB: IRNN outputs (128 ch)
// tf32(rna) weights, chunked+permuted: [ch][tap(9)][co(32)][k'(8)]
__device__ __align__(16) float g_win_cv[4*9*32*8];    // CIN=32  (4 chunks)
__device__ __align__(16) float g_w2_cv[16*9*32*8];    // CIN=128 (16 chunks)
__device__ __align__(16) float g_w3_cv[16*9*32*8];

__device__ __forceinline__ uint32_t f2tf32(float f) {
    uint32_t t;
    asm("cvt.rna.tf32.f32 %0, %1;" : "=r"(t) : "f"(f));
    return t;
}
__device__ __forceinline__ uint32_t smem_u32(const void* p) {
    uint32_t a;
    asm("{ .reg .u64 t; cvta.to.shared.u64 t, %1; cvt.u32.u64 %0, t; }" : "=r"(a) : "l"(p));
    return a;
}
__device__ __forceinline__ void cp16(uint32_t dst, const void* src, bool pred) {
    int sz = pred ? 16 : 0;
    asm volatile("cp.async.cg.shared.global [%0], [%1], 16, %2;"
                 :: "r"(dst), "l"(src), "r"(sz) : "memory");
}
__device__ __forceinline__ void cp_commit() {
    asm volatile("cp.async.commit_group;" ::: "memory");
}
template<int N>
__device__ __forceinline__ void cp_wait() {
    asm volatile("cp.async.wait_group %0;" :: "n"(N) : "memory");
}

// ---------------------------------------------------------------------------
// Weight prep: OIHW fp32 -> [ch][tap][co][k'] tf32(rna), k' = 2*(k&3)+(k>>2)
// ---------------------------------------------------------------------------
template<int CIN>
__global__ void prep_w_kernel(const float* __restrict__ w, float* __restrict__ wbuf)
{
    int idx = blockIdx.x * 256 + threadIdx.x;
    if (idx >= 32*CIN*9) return;
    int dx = idx % 3;
    int dy = (idx / 3) % 3;
    int ci = (idx / 9) % CIN;
    int co = idx / (9*CIN);
    int ch = ci >> 3, k = ci & 7;
    int kp = 2*(k & 3) + (k >> 2);
    int tap = dy*3 + dx;
    ((uint32_t*)wbuf)[((ch*9 + tap)*32 + co)*8 + kp] = f2tf32(w[idx]);
}

// ---------------------------------------------------------------------------
// tf32 mma.sync implicit-GEMM 3x3 conv, pad=1, Cout=32.
// CTA: 256 thr (8 warps), tile 128x4 = 512 px. 3-stage cp.async pipeline,
// single barrier per chunk + one barrier at tile end (prevents the next
// tile's prefetch racing the last chunk's reads — 15%3 == 0!).
// OUTMODE: 0 = plain store, 2 = relu + fused 1x1 conv_out + sigmoid.
// ---------------------------------------------------------------------------
template<int CIN, int OUTMODE>
__global__ void __launch_bounds__(256, 2) conv_mma_kernel(
    const float* __restrict__ in, const float* __restrict__ wbuf,
    float* __restrict__ outp, const float* __restrict__ w_out)
{
    constexpr int NCH = CIN/8;
    constexpr int INW = 6*8*136;       // 6528 words per input buffer
    constexpr int WW  = 9*32*8;        // 2304 words per weight slice
    extern __shared__ float sm[];
    float* s_in[3] = { sm, sm + INW, sm + 2*INW };
    float* s_w[3]  = { sm + 3*INW, sm + 3*INW + WW, sm + 3*INW + 2*WW };
    const uint32_t s_in_u[3] = { smem_u32(s_in[0]), smem_u32(s_in[1]), smem_u32(s_in[2]) };
    const uint32_t s_w_u[3]  = { smem_u32(s_w[0]),  smem_u32(s_w[1]),  smem_u32(s_w[2])  };

    const int tid = threadIdx.x;
    const int lane = tid & 31;
    const int wrp = tid >> 5;
    const int r4 = lane >> 2;     // 0..7
    const int c4 = lane & 3;      // 0..3
    const int ywarp = wrp >> 1;          // 0..3
    const int xwarp = (wrp & 1) * 64;    // 0 or 64

    float wo0[4], wo1[4];
    if (OUTMODE == 2) {
#pragma unroll
        for (int nb = 0; nb < 4; nb++) {
            wo0[nb] = __ldg(w_out + nb*8 + c4*2);
            wo1[nb] = __ldg(w_out + nb*8 + c4*2 + 1);
        }
    }

    for (int tg = blockIdx.x; tg < 1024; tg += gridDim.x) {
        const int b  = tg >> 7;
        const int ty = (tg >> 1) & 63;
        const int tx = tg & 1;
        const int x0 = tx*128, y0 = ty*4;

        auto STAGE = [&](int ch) {
            const int bufi = ch % 3;
            const float* base = in + (size_t)(b*CIN + ch*8)*HW;
#pragma unroll
            for (int k = 0; k < 7; k++) {
                int t = tid + k*256;
                if (t < 1632) {
                    int iy = t / 272;
                    int r  = t - iy*272;
                    int ci = r / 34;
                    int f4 = r - ci*34;
                    int gy = y0 - 1 + iy;
                    int gxs = x0 - 4 + f4*4;
                    bool pred = ((unsigned)gy < 256u) && ((unsigned)gxs <= 252u);
                    const float* src = base + (size_t)ci*HW
                                     + (pred ? (gy*256 + gxs) : 0);
                    cp16(s_in_u[bufi] + (((iy*8 + ci)*136 + f4*4) << 2), src, pred);
                }
            }
            const float* wsrc = wbuf + (size_t)ch*WW;
#pragma unroll
            for (int k = 0; k < 3; k++) {
                int t = tid + k*256;
                if (t < 576)
                    cp16(s_w_u[bufi] + (t << 4), wsrc + t*4, true);
            }
            cp_commit();
        };

        float acc[4][4][4];
#pragma unroll
        for (int mb = 0; mb < 4; mb++)
#pragma unroll
            for (int nb = 0; nb < 4; nb++)
#pragma unroll
                for (int q = 0; q < 4; q++) acc[mb][nb][q] = 0.f;

        STAGE(0);
        if (NCH > 1) STAGE(1);

        for (int ch = 0; ch < NCH; ch++) {
            if (ch == NCH - 1) cp_wait<0>(); else cp_wait<1>();
            __syncthreads();
            if (ch + 2 < NCH) STAGE(ch + 2);

            const uint32_t* bufI = (const uint32_t*)s_in[ch % 3];
            const uint32_t* bw   = (const uint32_t*)s_w[ch % 3];

#pragma unroll
            for (int dy = 0; dy < 3; dy++) {
#pragma unroll
                for (int dx = 0; dx < 3; dx++) {
                    const int tap = dy*3 + dx;
                    uint32_t a[4][4];
#pragma unroll
                    for (int mb = 0; mb < 4; mb++) {
                        int iy = ywarp + dy;
                        int sx = xwarp + mb*16 + r4 + dx + 3;
                        int b0 = (iy*8 + c4)*136 + sx;
                        a[mb][0] = bufI[b0];
                        a[mb][1] = bufI[b0 + 8];
                        a[mb][2] = bufI[b0 + 4*136];
                        a[mb][3] = bufI[b0 + 4*136 + 8];
                    }
#pragma unroll
                    for (int nb = 0; nb < 4; nb++) {
                        uint2 bb = *(const uint2*)&bw[((tap*32 + nb*8 + r4) << 3) + c4*2];
#pragma unroll
                        for (int mb = 0; mb < 4; mb++) {
                            asm("mma.sync.aligned.m16n8k8.row.col.f32.tf32.tf32.f32 "
                                "{%0,%1,%2,%3}, {%4,%5,%6,%7}, {%8,%9}, {%0,%1,%2,%3};"
                                : "+f"(acc[mb][nb][0]), "+f"(acc[mb][nb][1]),
                                  "+f"(acc[mb][nb][2]), "+f"(acc[mb][nb][3])
                                : "r"(a[mb][0]), "r"(a[mb][1]),
                                  "r"(a[mb][2]), "r"(a[mb][3]),
                                  "r"(bb.x), "r"(bb.y));
                        }
                    }
                }
            }
        }

        if (OUTMODE == 2) {
            // fused: relu -> 1x1 conv_out -> sigmoid. Pixel p's 32 channels
            // live across the 4 lanes of its c4-group (8 per lane).
            float* outO = outp + (size_t)b*HW + (y0 + ywarp)*256 + x0;
#pragma unroll
            for (int mb = 0; mb < 4; mb++) {
                int px = xwarp + mb*16 + r4;
                float pp = 0.f, pq = 0.f;
#pragma unroll
                for (int nb = 0; nb < 4; nb++) {
                    pp = fmaf(wo0[nb], fmaxf(acc[mb][nb][0], 0.f), pp);
                    pp = fmaf(wo1[nb], fmaxf(acc[mb][nb][1], 0.f), pp);
                    pq = fmaf(wo0[nb], fmaxf(acc[mb][nb][2], 0.f), pq);
                    pq = fmaf(wo1[nb], fmaxf(acc[mb][nb][3], 0.f), pq);
                }
                pp += __shfl_xor_sync(0xFFFFFFFFu, pp, 1);
                pp += __shfl_xor_sync(0xFFFFFFFFu, pp, 2);
                pq += __shfl_xor_sync(0xFFFFFFFFu, pq, 1);
                pq += __shfl_xor_sync(0xFFFFFFFFu, pq, 2);
                if (c4 == 0) {
                    outO[px]     = 1.f / (1.f + expf(-pp));
                    outO[px + 8] = 1.f / (1.f + expf(-pq));
                }
            }
        } else {
#pragma unroll
            for (int mb = 0; mb < 4; mb++) {
                int px = xwarp + mb*16 + r4;
                float* orow = outp + (size_t)b*32*HW + (y0 + ywarp)*256 + x0 + px;
#pragma unroll
                for (int nb = 0; nb < 4; nb++) {
                    int co = nb*8 + c4*2;
                    orow[(size_t)co*HW]           = acc[mb][nb][0];
                    orow[(size_t)(co + 1)*HW]     = acc[mb][nb][1];
                    orow[(size_t)co*HW + 8]       = acc[mb][nb][2];
                    orow[(size_t)(co + 1)*HW + 8] = acc[mb][nb][3];
                }
            }
        }
        // CRITICAL: next tile's STAGE(0)/STAGE(1) reuse buffers the last
        // chunks just read (NCH-1 ≡ 0 mod 3). Barrier before reuse.
        __syncthreads();
    }
}

// ---------------------------------------------------------------------------
// H-direction scans. One block per (b,c,direction): blocks 0..255 = down,
// 256..511 = up. 256 threads = 256 columns.
// ---------------------------------------------------------------------------
__global__ void __launch_bounds__(256) hscan_kernel(
    const float* __restrict__ in, float* __restrict__ outp,
    const float* __restrict__ wp, const float* __restrict__ bp)
{
    int blk = blockIdx.x;
    int n = blk & 255;             // b*32 + c
    int b = n >> 5, c = n & 31;
    int w = threadIdx.x;
    const float* gin = in + (size_t)n*HW + w;

    if (blk < 256) {               // down (dir 2): rows 0..255, row 0 raw
        float* gd = outp + (size_t)(b*128 + 64 + c)*HW + w;
        float wc = wp[64 + c], bc = bp[64 + c];
        float h = gin[0];
        gd[0] = h;
#pragma unroll 8
        for (int i = 1; i < Hh; i++) {
            float x = gin[i*Ww];
            h = fmaxf(fmaf(wc, h, x + bc), 0.f);
            gd[i*Ww] = h;
        }
    } else {                       // up (dir 0): rows 255..0, row 255 raw
        float* gu = outp + (size_t)(b*128 + c)*HW + w;
        float wc = wp[c], bc = bp[c];
        float h = gin[(Hh-1)*Ww];
        gu[(Hh-1)*Ww] = h;
#pragma unroll 8
        for (int i = Hh - 2; i >= 0; i--) {
            float x = gin[i*Ww];
            h = fmaxf(fmaf(wc, h, x + bc), 0.f);
            gu[i*Ww] = h;
        }
    }
}

// ---------------------------------------------------------------------------
// W-direction scans. One block per (b,c) plane; 256 threads = 256 rows.
// X chunked by 32 with per-thread carry; stride-33 smem (conflict-free).
// ---------------------------------------------------------------------------
__global__ void __launch_bounds__(256) wscan_kernel(
    const float* __restrict__ in, float* __restrict__ outp,
    const float* __restrict__ wp, const float* __restrict__ bp)
{
    __shared__ float xs[256*33];
    int n = blockIdx.x;            // b*32 + c
    int b = n >> 5, c = n & 31;
    int t = threadIdx.x;
    const float* gin = in + (size_t)n*HW;
    float* gr = outp + (size_t)(b*128 + 32 + c)*HW;
    float* gl = outp + (size_t)(b*128 + 96 + c)*HW;

    // ---- right pass (dir 1): cols 0..255, col 0 raw ----
    {
        float wc = wp[32 + c], bc = bp[32 + c];
        float h = 0.f;
        for (int cx = 0; cx < 8; cx++) {
#pragma unroll
            for (int k = 0; k < 8; k++) {
                int i4 = t + k*256;
                int row = i4 >> 3, f4 = i4 & 7;
                float4 v = *(const float4*)(gin + row*256 + cx*32 + f4*4);
                float* d = &xs[row*33 + f4*4];
                d[0] = v.x; d[1] = v.y; d[2] = v.z; d[3] = v.w;
            }
            __syncthreads();
            float* xr = &xs[t*33];
            {
                float x = xr[0];
                h = (cx == 0) ? x : fmaxf(fmaf(wc, h, x + bc), 0.f);
                xr[0] = h;
            }
#pragma unroll
            for (int j = 1; j < 32; j++) {
                float x = xr[j];
                h = fmaxf(fmaf(wc, h, x + bc), 0.f);
                xr[j] = h;
            }
            __syncthreads();
#pragma unroll
            for (int k = 0; k < 8; k++) {
                int i4 = t + k*256;
                int row = i4 >> 3, f4 = i4 & 7;
                float* s = &xs[row*33 + f4*4];
                *(float4*)(gr + row*256 + cx*32 + f4*4)
                    = make_float4(s[0], s[1], s[2], s[3]);
            }
            __syncthreads();
        }
    }
    // ---- left pass (dir 3): cols 255..0, col 255 raw ----
    {
        float wc = wp[96 + c], bc = bp[96 + c];
        float h = 0.f;
        for (int cx = 7; cx >= 0; cx--) {
#pragma unroll
            for (int k = 0; k < 8; k++) {
                int i4 = t + k*256;
                int row = i4 >> 3, f4 = i4 & 7;
                float4 v = *(const float4*)(gin + row*256 + cx*32 + f4*4);
                float* d = &xs[row*33 + f4*4];
                d[0] = v.x; d[1] = v.y; d[2] = v.z; d[3] = v.w;
            }
            __syncthreads();
            float* xr = &xs[t*33];
            {
                float x = xr[31];
                h = (cx == 7) ? x : fmaxf(fmaf(wc, h, x + bc), 0.f);
                xr[31] = h;
            }
#pragma unroll
            for (int j = 30; j >= 0; j--) {
                float x = xr[j];
                h = fmaxf(fmaf(wc, h, x + bc), 0.f);
                xr[j] = h;
            }
            __syncthreads();
#pragma unroll
            for (int k = 0; k < 8; k++) {
                int i4 = t + k*256;
                int row = i4 >> 3, f4 = i4 & 7;
                float* s = &xs[row*33 + f4*4];
                *(float4*)(gl + row*256 + cx*32 + f4*4)
                    = make_float4(s[0], s[1], s[2], s[3]);
            }
            __syncthreads();
        }
    }
}

// ---------------------------------------------------------------------------
extern "C" void kernel_launch(void* const* d_in, const int* in_sizes, int n_in,
                              void* d_out, int out_size)
{
    const float* x     = (const float*)d_in[0];
    const float* w_in  = (const float*)d_in[1];
    const float* w2    = (const float*)d_in[2];
    const float* w3    = (const float*)d_in[3];
    const float* w_out = (const float*)d_in[4];
    const float* i1w   = (const float*)d_in[5];
    const float* i1b   = (const float*)d_in[6];
    const float* i2w   = (const float*)d_in[7];
    const float* i2b   = (const float*)d_in[8];
    float* out = (float*)d_out;

    float *dA, *dB, *dWin, *dW2, *dW3;
    cudaGetSymbolAddress((void**)&dA, g_bufA);
    cudaGetSymbolAddress((void**)&dB, g_bufB);
    cudaGetSymbolAddress((void**)&dWin, g_win_cv);
    cudaGetSymbolAddress((void**)&dW2, g_w2_cv);
    cudaGetSymbolAddress((void**)&dW3, g_w3_cv);

    const int SMEM = (3*6528 + 3*2304) * 4;   // 105984 B
    cudaFuncSetAttribute(conv_mma_kernel<32,0>,
                         cudaFuncAttributeMaxDynamicSharedMemorySize, SMEM);
    cudaFuncSetAttribute(conv_mma_kernel<128,0>,
                         cudaFuncAttributeMaxDynamicSharedMemorySize, SMEM);
    cudaFuncSetAttribute(conv_mma_kernel<128,2>,
                         cudaFuncAttributeMaxDynamicSharedMemorySize, SMEM);

    // weight prep (tf32 rna convert + chunk/permute)
    prep_w_kernel<32> <<<(32*32*9  + 255)/256, 256>>>(w_in, dWin);
    prep_w_kernel<128><<<(32*128*9 + 255)/256, 256>>>(w2, dW2);
    prep_w_kernel<128><<<(32*128*9 + 255)/256, 256>>>(w3, dW3);

    // 1. conv_in: x -> bufA
    conv_mma_kernel<32,0><<<296, 256, SMEM>>>(x, dWin, dA, nullptr);
    // 2. irnn1: bufA -> bufB
    hscan_kernel<<<512, 256>>>(dA, dB, i1w, i1b);
    wscan_kernel<<<256, 256>>>(dA, dB, i1w, i1b);
    // 3. conv2: bufB -> bufA
    conv_mma_kernel<128,0><<<296, 256, SMEM>>>(dB, dW2, dA, nullptr);
    // 4. irnn2: bufA -> bufB
    hscan_kernel<<<512, 256>>>(dA, dB, i2w, i2b);
    wscan_kernel<<<256, 256>>>(dA, dB, i2w, i2b);
    // 5. conv3 + relu + conv_out + sigmoid: bufB -> d_out
    conv_mma_kernel<128,2><<<296, 256, SMEM>>>(dB, dW3, out, w_out);
}

// round 8
// speedup vs baseline: 7.9781x; 1.2152x over previous
#include <cuda_runtime.h>
#include <cuda_fp16.h>
#include <math.h>
#include <stdint.h>

#define Bn 8
#define Cc 32
#define Hh 256
#define Ww 256
#define HW (Hh*Ww)

// ---------------------------------------------------------------------------
// Scratch buffers (allocation-free rule: __device__ globals)
// ---------------------------------------------------------------------------
__device__ __align__(16) float    g_bufA[Bn*Cc*HW];      // 67 MB: conv outputs fp32 (32 ch)
__device__ __align__(16) uint32_t g_bufB[Bn*64*HW];      // 134 MB: IRNN outputs, half2-packed (64 pair planes)
// tf32(rna) weights for conv_in: [ch(4)][tap(9)][co(32)][k'(8)]
__device__ __align__(16) float  g_win_cv[4*9*32*8];
// fp16 weights for conv2/conv3: [ch(8)][tap(9)][co(32)][slot(8) x half2]
__device__ __align__(16) __half g_w2_h[8*9*32*16];
__device__ __align__(16) __half g_w3_h[8*9*32*16];

__device__ __forceinline__ uint32_t f2tf32(float f) {
    uint32_t t;
    asm("cvt.rna.tf32.f32 %0, %1;" : "=r"(t) : "f"(f));
    return t;
}
__device__ __forceinline__ uint32_t smem_u32(const void* p) {
    uint32_t a;
    asm("{ .reg .u64 t; cvta.to.shared.u64 t, %1; cvt.u32.u64 %0, t; }" : "=r"(a) : "l"(p));
    return a;
}
__device__ __forceinline__ void cp16(uint32_t dst, const void* src, bool pred) {
    int sz = pred ? 16 : 0;
    asm volatile("cp.async.cg.shared.global [%0], [%1], 16, %2;"
                 :: "r"(dst), "l"(src), "r"(sz) : "memory");
}
__device__ __forceinline__ void cp_commit() {
    asm volatile("cp.async.commit_group;" ::: "memory");
}
template<int N>
__device__ __forceinline__ void cp_wait() {
    asm volatile("cp.async.wait_group %0;" :: "n"(N) : "memory");
}
__device__ __forceinline__ uint32_t packh2(float a, float b) {
    __half2 h = __floats2half2_rn(a, b);     // .x = a (low), .y = b (high)
    return *reinterpret_cast<uint32_t*>(&h);
}

// ---------------------------------------------------------------------------
// Weight prep (conv_in, tf32): OIHW fp32 -> [ch][tap][co][k'], k'=2*(k&3)+(k>>2)
// ---------------------------------------------------------------------------
__global__ void prep_w_tf32(const float* __restrict__ w, float* __restrict__ wbuf)
{
    int idx = blockIdx.x * 256 + threadIdx.x;
    if (idx >= 32*32*9) return;
    int dx = idx % 3;
    int dy = (idx / 3) % 3;
    int ci = (idx / 9) % 32;
    int co = idx / (9*32);
    int ch = ci >> 3, k = ci & 7;
    int kp = 2*(k & 3) + (k >> 2);
    ((uint32_t*)wbuf)[((ch*9 + dy*3 + dx)*32 + co)*8 + kp] = f2tf32(w[idx]);
}

// ---------------------------------------------------------------------------
// Weight prep (conv2/3, fp16): ci -> chunk ch=ci>>4, k=ci&15, pair p=k>>1,
// slot s = (p<4)? 2p : 2(p-4)+1 so a uint2 at 2*c4 yields (b0, b1).
// ---------------------------------------------------------------------------
__global__ void prep_w_f16(const float* __restrict__ w, __half* __restrict__ wbuf)
{
    int idx = blockIdx.x * 256 + threadIdx.x;
    if (idx >= 32*128*9) return;
    int dx = idx % 3;
    int dy = (idx / 3) % 3;
    int ci = (idx / 9) % 128;
    int co = idx / (9*128);
    int ch = ci >> 4, k = ci & 15;
    int p = k >> 1, hf = k & 1;
    int s = (p < 4) ? 2*p : 2*(p - 4) + 1;
    wbuf[(((ch*9 + dy*3 + dx)*32 + co)*8 + s)*2 + hf] = __float2half_rn(w[idx]);
}

// ---------------------------------------------------------------------------
// conv_in: tf32 mma implicit-GEMM, CIN=32 fp32 -> 32ch fp32 (bufA).
// ---------------------------------------------------------------------------
__global__ void __launch_bounds__(256, 2) conv_tf32_kernel(
    const float* __restrict__ in, const float* __restrict__ wbuf,
    float* __restrict__ outp)
{
    constexpr int NCH = 4;
    constexpr int INW = 6*8*136;
    constexpr int WW  = 9*32*8;
    extern __shared__ float sm[];
    float* s_in[3] = { sm, sm + INW, sm + 2*INW };
    float* s_w[3]  = { sm + 3*INW, sm + 3*INW + WW, sm + 3*INW + 2*WW };
    const uint32_t s_in_u[3] = { smem_u32(s_in[0]), smem_u32(s_in[1]), smem_u32(s_in[2]) };
    const uint32_t s_w_u[3]  = { smem_u32(s_w[0]),  smem_u32(s_w[1]),  smem_u32(s_w[2])  };

    const int tid = threadIdx.x;
    const int lane = tid & 31;
    const int wrp = tid >> 5;
    const int r4 = lane >> 2, c4 = lane & 3;
    const int ywarp = wrp >> 1;
    const int xwarp = (wrp & 1) * 64;

    for (int tg = blockIdx.x; tg < 1024; tg += gridDim.x) {
        const int b  = tg >> 7;
        const int ty = (tg >> 1) & 63;
        const int tx = tg & 1;
        const int x0 = tx*128, y0 = ty*4;

        auto STAGE = [&](int ch) {
            const int bufi = ch % 3;
            const float* base = in + (size_t)(b*32 + ch*8)*HW;
#pragma unroll
            for (int k = 0; k < 7; k++) {
                int t = tid + k*256;
                if (t < 1632) {
                    int iy = t / 272;
                    int r  = t - iy*272;
                    int ci = r / 34;
                    int f4 = r - ci*34;
                    int gy = y0 - 1 + iy;
                    int gxs = x0 - 4 + f4*4;
                    bool pred = ((unsigned)gy < 256u) && ((unsigned)gxs <= 252u);
                    const float* src = base + (size_t)ci*HW + (pred ? (gy*256 + gxs) : 0);
                    cp16(s_in_u[bufi] + (((iy*8 + ci)*136 + f4*4) << 2), src, pred);
                }
            }
            const float* wsrc = wbuf + (size_t)ch*WW;
#pragma unroll
            for (int k = 0; k < 3; k++) {
                int t = tid + k*256;
                if (t < 576) cp16(s_w_u[bufi] + (t << 4), wsrc + t*4, true);
            }
            cp_commit();
        };

        float acc[4][4][4];
#pragma unroll
        for (int mb = 0; mb < 4; mb++)
#pragma unroll
            for (int nb = 0; nb < 4; nb++)
#pragma unroll
                for (int q = 0; q < 4; q++) acc[mb][nb][q] = 0.f;

        STAGE(0); STAGE(1);

        for (int ch = 0; ch < NCH; ch++) {
            if (ch == NCH - 1) cp_wait<0>(); else cp_wait<1>();
            __syncthreads();
            if (ch + 2 < NCH) STAGE(ch + 2);

            const uint32_t* bufI = (const uint32_t*)s_in[ch % 3];
            const uint32_t* bw   = (const uint32_t*)s_w[ch % 3];
#pragma unroll
            for (int dy = 0; dy < 3; dy++)
#pragma unroll
            for (int dx = 0; dx < 3; dx++) {
                const int tap = dy*3 + dx;
                uint32_t a[4][4];
#pragma unroll
                for (int mb = 0; mb < 4; mb++) {
                    int iy = ywarp + dy;
                    int sx = xwarp + mb*16 + r4 + dx + 3;
                    int b0 = (iy*8 + c4)*136 + sx;
                    a[mb][0] = bufI[b0];
                    a[mb][1] = bufI[b0 + 8];
                    a[mb][2] = bufI[b0 + 4*136];
                    a[mb][3] = bufI[b0 + 4*136 + 8];
                }
#pragma unroll
                for (int nb = 0; nb < 4; nb++) {
                    uint2 bb = *(const uint2*)&bw[((tap*32 + nb*8 + r4) << 3) + c4*2];
#pragma unroll
                    for (int mb = 0; mb < 4; mb++) {
                        asm("mma.sync.aligned.m16n8k8.row.col.f32.tf32.tf32.f32 "
                            "{%0,%1,%2,%3}, {%4,%5,%6,%7}, {%8,%9}, {%0,%1,%2,%3};"
                            : "+f"(acc[mb][nb][0]), "+f"(acc[mb][nb][1]),
                              "+f"(acc[mb][nb][2]), "+f"(acc[mb][nb][3])
                            : "r"(a[mb][0]), "r"(a[mb][1]), "r"(a[mb][2]), "r"(a[mb][3]),
                              "r"(bb.x), "r"(bb.y));
                    }
                }
            }
        }

#pragma unroll
        for (int mb = 0; mb < 4; mb++) {
            int px = xwarp + mb*16 + r4;
            float* orow = outp + (size_t)b*32*HW + (y0 + ywarp)*256 + x0 + px;
#pragma unroll
            for (int nb = 0; nb < 4; nb++) {
                int co = nb*8 + c4*2;
                orow[(size_t)co*HW]           = acc[mb][nb][0];
                orow[(size_t)(co + 1)*HW]     = acc[mb][nb][1];
                orow[(size_t)co*HW + 8]       = acc[mb][nb][2];
                orow[(size_t)(co + 1)*HW + 8] = acc[mb][nb][3];
            }
        }
        __syncthreads();   // guard buffer ring across grid-stride tiles
    }
}

// ---------------------------------------------------------------------------
// conv2/conv3: fp16 mma m16n8k16 implicit-GEMM. Input = half2-packed bufB
// (64 pair planes). Chunk = 8 pair planes = 16 channels, NCH=8.
// OUTMODE 0: fp32 store to bufA.  OUTMODE 2: relu + 1x1 conv_out + sigmoid.
// ---------------------------------------------------------------------------
template<int OUTMODE>
__global__ void __launch_bounds__(256, 2) conv_f16_kernel(
    const uint32_t* __restrict__ in, const uint32_t* __restrict__ wbuf,
    float* __restrict__ outp, const float* __restrict__ w_out)
{
    constexpr int NCH = 8;
    constexpr int INW = 6*8*136;
    constexpr int WW  = 9*32*8;
    extern __shared__ float sm[];
    float* s_in[3] = { sm, sm + INW, sm + 2*INW };
    float* s_w[3]  = { sm + 3*INW, sm + 3*INW + WW, sm + 3*INW + 2*WW };
    const uint32_t s_in_u[3] = { smem_u32(s_in[0]), smem_u32(s_in[1]), smem_u32(s_in[2]) };
    const uint32_t s_w_u[3]  = { smem_u32(s_w[0]),  smem_u32(s_w[1]),  smem_u32(s_w[2])  };

    const int tid = threadIdx.x;
    const int lane = tid & 31;
    const int wrp = tid >> 5;
    const int r4 = lane >> 2, c4 = lane & 3;
    const int ywarp = wrp >> 1;
    const int xwarp = (wrp & 1) * 64;

    float wo0[4], wo1[4];
    if (OUTMODE == 2) {
#pragma unroll
        for (int nb = 0; nb < 4; nb++) {
            wo0[nb] = __ldg(w_out + nb*8 + c4*2);
            wo1[nb] = __ldg(w_out + nb*8 + c4*2 + 1);
        }
    }

    for (int tg = blockIdx.x; tg < 1024; tg += gridDim.x) {
        const int b  = tg >> 7;
        const int ty = (tg >> 1) & 63;
        const int tx = tg & 1;
        const int x0 = tx*128, y0 = ty*4;

        auto STAGE = [&](int ch) {
            const int bufi = ch % 3;
            const uint32_t* base = in + (size_t)(b*64 + ch*8)*HW;
#pragma unroll
            for (int k = 0; k < 7; k++) {
                int t = tid + k*256;
                if (t < 1632) {
                    int iy = t / 272;
                    int r  = t - iy*272;
                    int cpl = r / 34;
                    int f4 = r - cpl*34;
                    int gy = y0 - 1 + iy;
                    int gxs = x0 - 4 + f4*4;
                    bool pred = ((unsigned)gy < 256u) && ((unsigned)gxs <= 252u);
                    const uint32_t* src = base + (size_t)cpl*HW + (pred ? (gy*256 + gxs) : 0);
                    cp16(s_in_u[bufi] + (((iy*8 + cpl)*136 + f4*4) << 2), src, pred);
                }
            }
            const uint32_t* wsrc = wbuf + (size_t)ch*WW;
#pragma unroll
            for (int k = 0; k < 3; k++) {
                int t = tid + k*256;
                if (t < 576) cp16(s_w_u[bufi] + (t << 4), wsrc + t*4, true);
            }
            cp_commit();
        };

        float acc[4][4][4];
#pragma unroll
        for (int mb = 0; mb < 4; mb++)
#pragma unroll
            for (int nb = 0; nb < 4; nb++)
#pragma unroll
                for (int q = 0; q < 4; q++) acc[mb][nb][q] = 0.f;

        STAGE(0); STAGE(1);

        for (int ch = 0; ch < NCH; ch++) {
            if (ch == NCH - 1) cp_wait<0>(); else cp_wait<1>();
            __syncthreads();
            if (ch + 2 < NCH) STAGE(ch + 2);

            const uint32_t* bufI = (const uint32_t*)s_in[ch % 3];
            const uint32_t* bw   = (const uint32_t*)s_w[ch % 3];
#pragma unroll
            for (int dy = 0; dy < 3; dy++)
#pragma unroll
            for (int dx = 0; dx < 3; dx++) {
                const int tap = dy*3 + dx;
                uint32_t a[4][4];
#pragma unroll
                for (int mb = 0; mb < 4; mb++) {
                    int iy = ywarp + dy;
                    int sx = xwarp + mb*16 + r4 + dx + 3;
                    int b0 = (iy*8 + c4)*136 + sx;
                    a[mb][0] = bufI[b0];            // k = 2c4,2c4+1   row px
                    a[mb][1] = bufI[b0 + 8];        //                 row px+8
                    a[mb][2] = bufI[b0 + 4*136];    // k = 2c4+8,+9    row px
                    a[mb][3] = bufI[b0 + 4*136 + 8];
                }
#pragma unroll
                for (int nb = 0; nb < 4; nb++) {
                    uint2 bb = *(const uint2*)&bw[((tap*32 + nb*8 + r4) << 3) + c4*2];
#pragma unroll
                    for (int mb = 0; mb < 4; mb++) {
                        asm("mma.sync.aligned.m16n8k16.row.col.f32.f16.f16.f32 "
                            "{%0,%1,%2,%3}, {%4,%5,%6,%7}, {%8,%9}, {%0,%1,%2,%3};"
                            : "+f"(acc[mb][nb][0]), "+f"(acc[mb][nb][1]),
                              "+f"(acc[mb][nb][2]), "+f"(acc[mb][nb][3])
                            : "r"(a[mb][0]), "r"(a[mb][1]), "r"(a[mb][2]), "r"(a[mb][3]),
                              "r"(bb.x), "r"(bb.y));
                    }
                }
            }
        }

        if (OUTMODE == 2) {
            float* outO = outp + (size_t)b*HW + (y0 + ywarp)*256 + x0;
#pragma unroll
            for (int mb = 0; mb < 4; mb++) {
                int px = xwarp + mb*16 + r4;
                float pp = 0.f, pq = 0.f;
#pragma unroll
                for (int nb = 0; nb < 4; nb++) {
                    pp = fmaf(wo0[nb], fmaxf(acc[mb][nb][0], 0.f), pp);
                    pp = fmaf(wo1[nb], fmaxf(acc[mb][nb][1], 0.f), pp);
                    pq = fmaf(wo0[nb], fmaxf(acc[mb][nb][2], 0.f), pq);
                    pq = fmaf(wo1[nb], fmaxf(acc[mb][nb][3], 0.f), pq);
                }
                pp += __shfl_xor_sync(0xFFFFFFFFu, pp, 1);
                pp += __shfl_xor_sync(0xFFFFFFFFu, pp, 2);
                pq += __shfl_xor_sync(0xFFFFFFFFu, pq, 1);
                pq += __shfl_xor_sync(0xFFFFFFFFu, pq, 2);
                if (c4 == 0) {
                    outO[px]     = 1.f / (1.f + expf(-pp));
                    outO[px + 8] = 1.f / (1.f + expf(-pq));
                }
            }
        } else {
#pragma unroll
            for (int mb = 0; mb < 4; mb++) {
                int px = xwarp + mb*16 + r4;
                float* orow = outp + (size_t)b*32*HW + (y0 + ywarp)*256 + x0 + px;
#pragma unroll
                for (int nb = 0; nb < 4; nb++) {
                    int co = nb*8 + c4*2;
                    orow[(size_t)co*HW]           = acc[mb][nb][0];
                    orow[(size_t)(co + 1)*HW]     = acc[mb][nb][1];
                    orow[(size_t)co*HW + 8]       = acc[mb][nb][2];
                    orow[(size_t)(co + 1)*HW + 8] = acc[mb][nb][3];
                }
            }
        }
        __syncthreads();
    }
}

// ---------------------------------------------------------------------------
// H-scans -> packed half2. Block = (dir, b, cp): 256 blocks, 256 thr = columns.
// Each thread scans channels 2cp and 2cp+1 together, writes one half2 plane.
// dir planes: up=0, right=1, down=2, left=3; pair plane = b*64 + dir*16 + cp.
// ---------------------------------------------------------------------------
__global__ void __launch_bounds__(256) hscan_kernel(
    const float* __restrict__ in, uint32_t* __restrict__ outp,
    const float* __restrict__ wp, const float* __restrict__ bp)
{
    int blk = blockIdx.x;
    int d = blk >> 7;              // 0 = down, 1 = up
    int n = blk & 127;
    int b = n >> 4, cp = n & 15;
    int w = threadIdx.x;
    const float* g0 = in + (size_t)(b*32 + 2*cp)*HW + w;
    const float* g1 = g0 + HW;

    if (d == 0) {                  // down (dir 2)
        uint32_t* gd = outp + (size_t)(b*64 + 32 + cp)*HW + w;
        float wc0 = wp[64 + 2*cp], bc0 = bp[64 + 2*cp];
        float wc1 = wp[64 + 2*cp + 1], bc1 = bp[64 + 2*cp + 1];
        float h0 = g0[0], h1 = g1[0];
        gd[0] = packh2(h0, h1);
#pragma unroll 8
        for (int i = 1; i < Hh; i++) {
            float x0 = g0[i*Ww], x1 = g1[i*Ww];
            h0 = fmaxf(fmaf(wc0, h0, x0 + bc0), 0.f);
            h1 = fmaxf(fmaf(wc1, h1, x1 + bc1), 0.f);
            gd[i*Ww] = packh2(h0, h1);
        }
    } else {                       // up (dir 0)
        uint32_t* gu = outp + (size_t)(b*64 + cp)*HW + w;
        float wc0 = wp[2*cp], bc0 = bp[2*cp];
        float wc1 = wp[2*cp + 1], bc1 = bp[2*cp + 1];
        float h0 = g0[(Hh-1)*Ww], h1 = g1[(Hh-1)*Ww];
        gu[(Hh-1)*Ww] = packh2(h0, h1);
#pragma unroll 8
        for (int i = Hh - 2; i >= 0; i--) {
            float x0 = g0[i*Ww], x1 = g1[i*Ww];
            h0 = fmaxf(fmaf(wc0, h0, x0 + bc0), 0.f);
            h1 = fmaxf(fmaf(wc1, h1, x1 + bc1), 0.f);
            gu[i*Ww] = packh2(h0, h1);
        }
    }
}

// ---------------------------------------------------------------------------
// W-scans -> packed half2. Block per (b,cp): 128 blocks, 256 thr = rows.
// Two fp32 planes staged in smem (stride 33), scanned, packed on store.
// ---------------------------------------------------------------------------
__global__ void __launch_bounds__(256) wscan_kernel(
    const float* __restrict__ in, uint32_t* __restrict__ outp,
    const float* __restrict__ wp, const float* __restrict__ bp)
{
    extern __shared__ float xs[];            // xs0[256*33] + xs1[256*33]
    float* xs0 = xs;
    float* xs1 = xs + 8448;
    int n = blockIdx.x;
    int b = n >> 4, cp = n & 15;
    int t = threadIdx.x;
    const float* g0 = in + (size_t)(b*32 + 2*cp)*HW;
    const float* g1 = g0 + HW;
    uint32_t* gr = outp + (size_t)(b*64 + 16 + cp)*HW;   // right (dir 1)
    uint32_t* gl = outp + (size_t)(b*64 + 48 + cp)*HW;   // left  (dir 3)

#pragma unroll 1
    for (int pass = 0; pass < 2; pass++) {
        const bool rightP = (pass == 0);
        float wc0 = wp[(rightP ? 32 : 96) + 2*cp], bc0 = bp[(rightP ? 32 : 96) + 2*cp];
        float wc1 = wp[(rightP ? 32 : 96) + 2*cp + 1], bc1 = bp[(rightP ? 32 : 96) + 2*cp + 1];
        uint32_t* go = rightP ? gr : gl;
        float h0 = 0.f, h1 = 0.f;
        for (int s = 0; s < 8; s++) {
            int cx = rightP ? s : 7 - s;
#pragma unroll
            for (int k = 0; k < 8; k++) {
                int i4 = t + k*256;
                int row = i4 >> 3, f4 = i4 & 7;
                float4 v0 = *(const float4*)(g0 + row*256 + cx*32 + f4*4);
                float4 v1 = *(const float4*)(g1 + row*256 + cx*32 + f4*4);
                float* d0 = &xs0[row*33 + f4*4];
                float* d1 = &xs1[row*33 + f4*4];
                d0[0]=v0.x; d0[1]=v0.y; d0[2]=v0.z; d0[3]=v0.w;
                d1[0]=v1.x; d1[1]=v1.y; d1[2]=v1.z; d1[3]=v1.w;
            }
            __syncthreads();
            float* r0 = &xs0[t*33];
            float* r1 = &xs1[t*33];
            if (rightP) {
                { float x0 = r0[0], x1 = r1[0];
                  if (s == 0) { h0 = x0; h1 = x1; }
                  else { h0 = fmaxf(fmaf(wc0, h0, x0 + bc0), 0.f);
                         h1 = fmaxf(fmaf(wc1, h1, x1 + bc1), 0.f); }
                  r0[0] = h0; r1[0] = h1; }
#pragma unroll
                for (int j = 1; j < 32; j++) {
                    float x0 = r0[j], x1 = r1[j];
                    h0 = fmaxf(fmaf(wc0, h0, x0 + bc0), 0.f);
                    h1 = fmaxf(fmaf(wc1, h1, x1 + bc1), 0.f);
                    r0[j] = h0; r1[j] = h1;
                }
            } else {
                { float x0 = r0[31], x1 = r1[31];
                  if (s == 0) { h0 = x0; h1 = x1; }
                  else { h0 = fmaxf(fmaf(wc0, h0, x0 + bc0), 0.f);
                         h1 = fmaxf(fmaf(wc1, h1, x1 + bc1), 0.f); }
                  r0[31] = h0; r1[31] = h1; }
#pragma unroll
                for (int j = 30; j >= 0; j--) {
                    float x0 = r0[j], x1 = r1[j];
                    h0 = fmaxf(fmaf(wc0, h0, x0 + bc0), 0.f);
                    h1 = fmaxf(fmaf(wc1, h1, x1 + bc1), 0.f);
                    r0[j] = h0; r1[j] = h1;
                }
            }
            __syncthreads();
#pragma unroll
            for (int k = 0; k < 8; k++) {
                int i4 = t + k*256;
                int row = i4 >> 3, f4 = i4 & 7;
                float* s0 = &xs0[row*33 + f4*4];
                float* s1 = &xs1[row*33 + f4*4];
                uint4 d;
                d.x = packh2(s0[0], s1[0]);
                d.y = packh2(s0[1], s1[1]);
                d.z = packh2(s0[2], s1[2]);
                d.w = packh2(s0[3], s1[3]);
                *(uint4*)(go + row*256 + cx*32 + f4*4) = d;
            }
            __syncthreads();
        }
    }
}

// ---------------------------------------------------------------------------
extern "C" void kernel_launch(void* const* d_in, const int* in_sizes, int n_in,
                              void* d_out, int out_size)
{
    const float* x     = (const float*)d_in[0];
    const float* w_in  = (const float*)d_in[1];
    const float* w2    = (const float*)d_in[2];
    const float* w3    = (const float*)d_in[3];
    const float* w_out = (const float*)d_in[4];
    const float* i1w   = (const float*)d_in[5];
    const float* i1b   = (const float*)d_in[6];
    const float* i2w   = (const float*)d_in[7];
    const float* i2b   = (const float*)d_in[8];
    float* out = (float*)d_out;

    float *dA, *dWin;
    uint32_t *dB;
    __half *dW2, *dW3;
    cudaGetSymbolAddress((void**)&dA, g_bufA);
    cudaGetSymbolAddress((void**)&dB, g_bufB);
    cudaGetSymbolAddress((void**)&dWin, g_win_cv);
    cudaGetSymbolAddress((void**)&dW2, g_w2_h);
    cudaGetSymbolAddress((void**)&dW3, g_w3_h);

    const int SMEMC = (3*6528 + 3*2304) * 4;   // 105984 B (both conv kernels)
    const int SMEMW = 2*8448*4;                //  67584 B (wscan)
    cudaFuncSetAttribute(conv_tf32_kernel,
                         cudaFuncAttributeMaxDynamicSharedMemorySize, SMEMC);
    cudaFuncSetAttribute(conv_f16_kernel<0>,
                         cudaFuncAttributeMaxDynamicSharedMemorySize, SMEMC);
    cudaFuncSetAttribute(conv_f16_kernel<2>,
                         cudaFuncAttributeMaxDynamicSharedMemorySize, SMEMC);
    cudaFuncSetAttribute(wscan_kernel,
                         cudaFuncAttributeMaxDynamicSharedMemorySize, SMEMW);

    // weight prep
    prep_w_tf32<<<(32*32*9  + 255)/256, 256>>>(w_in, dWin);
    prep_w_f16 <<<(32*128*9 + 255)/256, 256>>>(w2, dW2);
    prep_w_f16 <<<(32*128*9 + 255)/256, 256>>>(w3, dW3);

    // 1. conv_in: x -> bufA (fp32)
    conv_tf32_kernel<<<296, 256, SMEMC>>>(x, dWin, dA);
    // 2. irnn1: bufA -> bufB (half2 packed)
    hscan_kernel<<<256, 256>>>(dA, dB, i1w, i1b);
    wscan_kernel<<<128, 256, SMEMW>>>(dA, dB, i1w, i1b);
    // 3. conv2: bufB -> bufA (fp32)
    conv_f16_kernel<0><<<296, 256, SMEMC>>>(dB, (const uint32_t*)dW2, dA, nullptr);
    // 4. irnn2: bufA -> bufB
    hscan_kernel<<<256, 256>>>(dA, dB, i2w, i2b);
    wscan_kernel<<<128, 256, SMEMW>>>(dA, dB, i2w, i2b);
    // 5. conv3 + relu + conv_out + sigmoid: bufB -> d_out
    conv_f16_kernel<2><<<296, 256, SMEMC>>>(dB, (const uint32_t*)dW3, out, w_out);
}

// round 9
// speedup vs baseline: 10.8202x; 1.3562x over previous
#include <cuda_runtime.h>
#include <cuda_fp16.h>
#include <math.h>
#include <stdint.h>

#define Bn 8
#define Cc 32
#define Hh 256
#define Ww 256
#define HW (Hh*Ww)

// ---------------------------------------------------------------------------
// Scratch buffers (allocation-free rule: __device__ globals). Everything
// inter-kernel is half2-packed pair planes: plane (b*NP + c/2) holds
// channels (c, c+1) as (lo, hi) halves.
// ---------------------------------------------------------------------------
__device__ __align__(16) uint32_t g_xpk[Bn*16*HW];    //  33 MB: packed x
__device__ __align__(16) uint32_t g_bufA[Bn*16*HW];   //  33 MB: conv outputs (16 pair planes)
__device__ __align__(16) uint32_t g_bufB[Bn*64*HW];   // 134 MB: IRNN outputs (64 pair planes)
// fp16 weights: [ch][tap(9)][co(32)][slot(8) x half2]
__device__ __align__(16) __half g_win_h[2*9*32*16];   // CIN=32  (2 chunks)
__device__ __align__(16) __half g_w2_h[8*9*32*16];    // CIN=128 (8 chunks)
__device__ __align__(16) __half g_w3_h[8*9*32*16];

__device__ __forceinline__ uint32_t smem_u32(const void* p) {
    uint32_t a;
    asm("{ .reg .u64 t; cvta.to.shared.u64 t, %1; cvt.u32.u64 %0, t; }" : "=r"(a) : "l"(p));
    return a;
}
__device__ __forceinline__ void cp16(uint32_t dst, const void* src, bool pred) {
    int sz = pred ? 16 : 0;
    asm volatile("cp.async.cg.shared.global [%0], [%1], 16, %2;"
                 :: "r"(dst), "l"(src), "r"(sz) : "memory");
}
__device__ __forceinline__ void cp_commit() {
    asm volatile("cp.async.commit_group;" ::: "memory");
}
template<int N>
__device__ __forceinline__ void cp_wait() {
    asm volatile("cp.async.wait_group %0;" :: "n"(N) : "memory");
}
__device__ __forceinline__ uint32_t packh2(float a, float b) {
    __half2 h = __floats2half2_rn(a, b);
    return *reinterpret_cast<uint32_t*>(&h);
}
__device__ __forceinline__ float2 unpackh2(uint32_t w) {
    __half2 h = *reinterpret_cast<__half2*>(&w);
    return __half22float2(h);
}

// ---------------------------------------------------------------------------
// Pack x (fp32 NCHW) -> half2 pair planes. One thread = 4 pixels.
// ---------------------------------------------------------------------------
__global__ void __launch_bounds__(256) pack_x_kernel(
    const float* __restrict__ x, uint32_t* __restrict__ xp)
{
    int idx = blockIdx.x * 256 + threadIdx.x;       // over Bn*16*HW/4
    int p4 = idx & (HW/4 - 1);
    int pl = idx >> 14;                              // b*16 + cp
    const float* g0 = x + (size_t)pl*2*HW + p4*4;
    const float* g1 = g0 + HW;
    float4 v0 = *(const float4*)g0;
    float4 v1 = *(const float4*)g1;
    uint4 d;
    d.x = packh2(v0.x, v1.x);
    d.y = packh2(v0.y, v1.y);
    d.z = packh2(v0.z, v1.z);
    d.w = packh2(v0.w, v1.w);
    *(uint4*)(xp + (size_t)pl*HW + p4*4) = d;
}

// ---------------------------------------------------------------------------
// Weight prep fp16: ci -> chunk ch=ci>>4, k=ci&15, pair p=k>>1,
// slot s=(p<4)?2p:2(p-4)+1 so a uint2 at 2*c4 yields (b0,b1) fragments.
// ---------------------------------------------------------------------------
template<int CIN>
__global__ void prep_w_f16(const float* __restrict__ w, __half* __restrict__ wbuf)
{
    int idx = blockIdx.x * 256 + threadIdx.x;
    if (idx >= 32*CIN*9) return;
    int dx = idx % 3;
    int dy = (idx / 3) % 3;
    int ci = (idx / 9) % CIN;
    int co = idx / (9*CIN);
    int ch = ci >> 4, k = ci & 15;
    int p = k >> 1, hf = k & 1;
    int s = (p < 4) ? 2*p : 2*(p - 4) + 1;
    wbuf[(((ch*9 + dy*3 + dx)*32 + co)*8 + s)*2 + hf] = __float2half_rn(w[idx]);
}

// ---------------------------------------------------------------------------
// fp16 mma m16n8k16 implicit-GEMM 3x3 conv, pad=1, Cout=32.
// CTA: 256 thr, tile 128x4 = 512 px. Input: NPL pair planes per batch,
// chunk = 8 pair planes (16 ch), NCH chunks. 3-buffer cp.async ring.
// OUTMODE 0: packed half2 store (16 pair planes). 2: relu+1x1+sigmoid fp32.
// ---------------------------------------------------------------------------
template<int NPL, int NCH, int OUTMODE>
__global__ void __launch_bounds__(256, 2) conv_f16_kernel(
    const uint32_t* __restrict__ in, const uint32_t* __restrict__ wbuf,
    void* __restrict__ outp, const float* __restrict__ w_out)
{
    constexpr int INW = 6*8*136;
    constexpr int WW  = 9*32*8;
    extern __shared__ float sm[];
    float* s_in[3] = { sm, sm + INW, sm + 2*INW };
    float* s_w[3]  = { sm + 3*INW, sm + 3*INW + WW, sm + 3*INW + 2*WW };
    const uint32_t s_in_u[3] = { smem_u32(s_in[0]), smem_u32(s_in[1]), smem_u32(s_in[2]) };
    const uint32_t s_w_u[3]  = { smem_u32(s_w[0]),  smem_u32(s_w[1]),  smem_u32(s_w[2])  };

    const int tid = threadIdx.x;
    const int lane = tid & 31;
    const int wrp = tid >> 5;
    const int r4 = lane >> 2, c4 = lane & 3;
    const int ywarp = wrp >> 1;
    const int xwarp = (wrp & 1) * 64;

    float wo0[4], wo1[4];
    if (OUTMODE == 2) {
#pragma unroll
        for (int nb = 0; nb < 4; nb++) {
            wo0[nb] = __ldg(w_out + nb*8 + c4*2);
            wo1[nb] = __ldg(w_out + nb*8 + c4*2 + 1);
        }
    }

    for (int tg = blockIdx.x; tg < 1024; tg += gridDim.x) {
        const int b  = tg >> 7;
        const int ty = (tg >> 1) & 63;
        const int tx = tg & 1;
        const int x0 = tx*128, y0 = ty*4;

        auto STAGE = [&](int ch) {
            const int bufi = ch % 3;
            const uint32_t* base = in + (size_t)(b*NPL + ch*8)*HW;
#pragma unroll
            for (int k = 0; k < 7; k++) {
                int t = tid + k*256;
                if (t < 1632) {
                    int iy = t / 272;
                    int r  = t - iy*272;
                    int cpl = r / 34;
                    int f4 = r - cpl*34;
                    int gy = y0 - 1 + iy;
                    int gxs = x0 - 4 + f4*4;
                    bool pred = ((unsigned)gy < 256u) && ((unsigned)gxs <= 252u);
                    const uint32_t* src = base + (size_t)cpl*HW + (pred ? (gy*256 + gxs) : 0);
                    cp16(s_in_u[bufi] + (((iy*8 + cpl)*136 + f4*4) << 2), src, pred);
                }
            }
            const uint32_t* wsrc = wbuf + (size_t)ch*WW;
#pragma unroll
            for (int k = 0; k < 3; k++) {
                int t = tid + k*256;
                if (t < 576) cp16(s_w_u[bufi] + (t << 4), wsrc + t*4, true);
            }
            cp_commit();
        };

        float acc[4][4][4];
#pragma unroll
        for (int mb = 0; mb < 4; mb++)
#pragma unroll
            for (int nb = 0; nb < 4; nb++)
#pragma unroll
                for (int q = 0; q < 4; q++) acc[mb][nb][q] = 0.f;

        STAGE(0);
        if (NCH > 1) STAGE(1);

        for (int ch = 0; ch < NCH; ch++) {
            if (ch == NCH - 1) cp_wait<0>(); else cp_wait<1>();
            __syncthreads();
            if (ch + 2 < NCH) STAGE(ch + 2);

            const uint32_t* bufI = (const uint32_t*)s_in[ch % 3];
            const uint32_t* bw   = (const uint32_t*)s_w[ch % 3];
#pragma unroll
            for (int dy = 0; dy < 3; dy++)
#pragma unroll
            for (int dx = 0; dx < 3; dx++) {
                const int tap = dy*3 + dx;
                uint32_t a[4][4];
#pragma unroll
                for (int mb = 0; mb < 4; mb++) {
                    int iy = ywarp + dy;
                    int sx = xwarp + mb*16 + r4 + dx + 3;
                    int b0 = (iy*8 + c4)*136 + sx;
                    a[mb][0] = bufI[b0];
                    a[mb][1] = bufI[b0 + 8];
                    a[mb][2] = bufI[b0 + 4*136];
                    a[mb][3] = bufI[b0 + 4*136 + 8];
                }
#pragma unroll
                for (int nb = 0; nb < 4; nb++) {
                    uint2 bb = *(const uint2*)&bw[((tap*32 + nb*8 + r4) << 3) + c4*2];
#pragma unroll
                    for (int mb = 0; mb < 4; mb++) {
                        asm("mma.sync.aligned.m16n8k16.row.col.f32.f16.f16.f32 "
                            "{%0,%1,%2,%3}, {%4,%5,%6,%7}, {%8,%9}, {%0,%1,%2,%3};"
                            : "+f"(acc[mb][nb][0]), "+f"(acc[mb][nb][1]),
                              "+f"(acc[mb][nb][2]), "+f"(acc[mb][nb][3])
                            : "r"(a[mb][0]), "r"(a[mb][1]), "r"(a[mb][2]), "r"(a[mb][3]),
                              "r"(bb.x), "r"(bb.y));
                    }
                }
            }
        }

        if (OUTMODE == 2) {
            float* outO = (float*)outp + (size_t)b*HW + (y0 + ywarp)*256 + x0;
#pragma unroll
            for (int mb = 0; mb < 4; mb++) {
                int px = xwarp + mb*16 + r4;
                float pp = 0.f, pq = 0.f;
#pragma unroll
                for (int nb = 0; nb < 4; nb++) {
                    pp = fmaf(wo0[nb], fmaxf(acc[mb][nb][0], 0.f), pp);
                    pp = fmaf(wo1[nb], fmaxf(acc[mb][nb][1], 0.f), pp);
                    pq = fmaf(wo0[nb], fmaxf(acc[mb][nb][2], 0.f), pq);
                    pq = fmaf(wo1[nb], fmaxf(acc[mb][nb][3], 0.f), pq);
                }
                pp += __shfl_xor_sync(0xFFFFFFFFu, pp, 1);
                pp += __shfl_xor_sync(0xFFFFFFFFu, pp, 2);
                pq += __shfl_xor_sync(0xFFFFFFFFu, pq, 1);
                pq += __shfl_xor_sync(0xFFFFFFFFu, pq, 2);
                if (c4 == 0) {
                    outO[px]     = 1.f / (1.f + expf(-pp));
                    outO[px + 8] = 1.f / (1.f + expf(-pq));
                }
            }
        } else {
            // packed half2 store: pair plane = b*16 + nb*4 + c4
            uint32_t* outP = (uint32_t*)outp;
#pragma unroll
            for (int mb = 0; mb < 4; mb++) {
                int px = xwarp + mb*16 + r4;
#pragma unroll
                for (int nb = 0; nb < 4; nb++) {
                    uint32_t* orow = outP + (size_t)(b*16 + nb*4 + c4)*HW
                                   + (y0 + ywarp)*256 + x0 + px;
                    orow[0] = packh2(acc[mb][nb][0], acc[mb][nb][1]);
                    orow[8] = packh2(acc[mb][nb][2], acc[mb][nb][3]);
                }
            }
        }
        __syncthreads();   // guard buffer ring across grid-stride tiles
    }
}

// ---------------------------------------------------------------------------
// H-scans: packed in (16 pair planes) -> packed out planes of bufB.
// Block = (dir, b, cp): 256 blocks, 256 thr = columns.
// ---------------------------------------------------------------------------
__global__ void __launch_bounds__(256) hscan_kernel(
    const uint32_t* __restrict__ in, uint32_t* __restrict__ outp,
    const float* __restrict__ wp, const float* __restrict__ bp)
{
    int blk = blockIdx.x;
    int d = blk >> 7;              // 0 = down, 1 = up
    int n = blk & 127;
    int b = n >> 4, cp = n & 15;
    int w = threadIdx.x;
    const uint32_t* g = in + (size_t)(b*16 + cp)*HW + w;

    if (d == 0) {                  // down (dir 2)
        uint32_t* gd = outp + (size_t)(b*64 + 32 + cp)*HW + w;
        float wc0 = wp[64 + 2*cp], bc0 = bp[64 + 2*cp];
        float wc1 = wp[64 + 2*cp + 1], bc1 = bp[64 + 2*cp + 1];
        float2 v = unpackh2(g[0]);
        float h0 = v.x, h1 = v.y;
        gd[0] = packh2(h0, h1);
#pragma unroll 8
        for (int i = 1; i < Hh; i++) {
            float2 x = unpackh2(g[i*Ww]);
            h0 = fmaxf(fmaf(wc0, h0, x.x + bc0), 0.f);
            h1 = fmaxf(fmaf(wc1, h1, x.y + bc1), 0.f);
            gd[i*Ww] = packh2(h0, h1);
        }
    } else {                       // up (dir 0)
        uint32_t* gu = outp + (size_t)(b*64 + cp)*HW + w;
        float wc0 = wp[2*cp], bc0 = bp[2*cp];
        float wc1 = wp[2*cp + 1], bc1 = bp[2*cp + 1];
        float2 v = unpackh2(g[(Hh-1)*Ww]);
        float h0 = v.x, h1 = v.y;
        gu[(Hh-1)*Ww] = packh2(h0, h1);
#pragma unroll 8
        for (int i = Hh - 2; i >= 0; i--) {
            float2 x = unpackh2(g[i*Ww]);
            h0 = fmaxf(fmaf(wc0, h0, x.x + bc0), 0.f);
            h1 = fmaxf(fmaf(wc1, h1, x.y + bc1), 0.f);
            gu[i*Ww] = packh2(h0, h1);
        }
    }
}

// ---------------------------------------------------------------------------
// W-scans: packed in -> packed out. Block per (b,cp): 128 blocks, 256 thr =
// rows. Packed words staged in smem (stride 33), scanned in fp32 registers.
// ---------------------------------------------------------------------------
__global__ void __launch_bounds__(256) wscan_kernel(
    const uint32_t* __restrict__ in, uint32_t* __restrict__ outp,
    const float* __restrict__ wp, const float* __restrict__ bp)
{
    __shared__ uint32_t xs[256*33];
    int n = blockIdx.x;
    int b = n >> 4, cp = n & 15;
    int t = threadIdx.x;
    const uint32_t* g = in + (size_t)(b*16 + cp)*HW;
    uint32_t* gr = outp + (size_t)(b*64 + 16 + cp)*HW;   // right (dir 1)
    uint32_t* gl = outp + (size_t)(b*64 + 48 + cp)*HW;   // left  (dir 3)

#pragma unroll 1
    for (int pass = 0; pass < 2; pass++) {
        const bool rightP = (pass == 0);
        float wc0 = wp[(rightP ? 32 : 96) + 2*cp], bc0 = bp[(rightP ? 32 : 96) + 2*cp];
        float wc1 = wp[(rightP ? 32 : 96) + 2*cp + 1], bc1 = bp[(rightP ? 32 : 96) + 2*cp + 1];
        uint32_t* go = rightP ? gr : gl;
        float h0 = 0.f, h1 = 0.f;
        for (int s = 0; s < 8; s++) {
            int cx = rightP ? s : 7 - s;
#pragma unroll
            for (int k = 0; k < 8; k++) {
                int i4 = t + k*256;
                int row = i4 >> 3, f4 = i4 & 7;
                uint4 v = *(const uint4*)(g + row*256 + cx*32 + f4*4);
                uint32_t* d = &xs[row*33 + f4*4];
                d[0] = v.x; d[1] = v.y; d[2] = v.z; d[3] = v.w;
            }
            __syncthreads();
            uint32_t* xr = &xs[t*33];
            if (rightP) {
                { float2 x = unpackh2(xr[0]);
                  if (s == 0) { h0 = x.x; h1 = x.y; }
                  else { h0 = fmaxf(fmaf(wc0, h0, x.x + bc0), 0.f);
                         h1 = fmaxf(fmaf(wc1, h1, x.y + bc1), 0.f); }
                  xr[0] = packh2(h0, h1); }
#pragma unroll
                for (int j = 1; j < 32; j++) {
                    float2 x = unpackh2(xr[j]);
                    h0 = fmaxf(fmaf(wc0, h0, x.x + bc0), 0.f);
                    h1 = fmaxf(fmaf(wc1, h1, x.y + bc1), 0.f);
                    xr[j] = packh2(h0, h1);
                }
            } else {
                { float2 x = unpackh2(xr[31]);
                  if (s == 0) { h0 = x.x; h1 = x.y; }
                  else { h0 = fmaxf(fmaf(wc0, h0, x.x + bc0), 0.f);
                         h1 = fmaxf(fmaf(wc1, h1, x.y + bc1), 0.f); }
                  xr[31] = packh2(h0, h1); }
#pragma unroll
                for (int j = 30; j >= 0; j--) {
                    float2 x = unpackh2(xr[j]);
                    h0 = fmaxf(fmaf(wc0, h0, x.x + bc0), 0.f);
                    h1 = fmaxf(fmaf(wc1, h1, x.y + bc1), 0.f);
                    xr[j] = packh2(h0, h1);
                }
            }
            __syncthreads();
#pragma unroll
            for (int k = 0; k < 8; k++) {
                int i4 = t + k*256;
                int row = i4 >> 3, f4 = i4 & 7;
                uint32_t* sp = &xs[row*33 + f4*4];
                *(uint4*)(go + row*256 + cx*32 + f4*4)
                    = make_uint4(sp[0], sp[1], sp[2], sp[3]);
            }
            __syncthreads();
        }
    }
}

// ---------------------------------------------------------------------------
extern "C" void kernel_launch(void* const* d_in, const int* in_sizes, int n_in,
                              void* d_out, int out_size)
{
    const float* x     = (const float*)d_in[0];
    const float* w_in  = (const float*)d_in[1];
    const float* w2    = (const float*)d_in[2];
    const float* w3    = (const float*)d_in[3];
    const float* w_out = (const float*)d_in[4];
    const float* i1w   = (const float*)d_in[5];
    const float* i1b   = (const float*)d_in[6];
    const float* i2w   = (const float*)d_in[7];
    const float* i2b   = (const float*)d_in[8];
    float* out = (float*)d_out;

    uint32_t *dXP, *dA, *dB;
    __half *dWin, *dW2, *dW3;
    cudaGetSymbolAddress((void**)&dXP, g_xpk);
    cudaGetSymbolAddress((void**)&dA, g_bufA);
    cudaGetSymbolAddress((void**)&dB, g_bufB);
    cudaGetSymbolAddress((void**)&dWin, g_win_h);
    cudaGetSymbolAddress((void**)&dW2, g_w2_h);
    cudaGetSymbolAddress((void**)&dW3, g_w3_h);

    const int SMEMC = (3*6528 + 3*2304) * 4;   // 105984 B
    cudaFuncSetAttribute((const void*)conv_f16_kernel<16,2,0>,
                         cudaFuncAttributeMaxDynamicSharedMemorySize, SMEMC);
    cudaFuncSetAttribute((const void*)conv_f16_kernel<64,8,0>,
                         cudaFuncAttributeMaxDynamicSharedMemorySize, SMEMC);
    cudaFuncSetAttribute((const void*)conv_f16_kernel<64,8,2>,
                         cudaFuncAttributeMaxDynamicSharedMemorySize, SMEMC);

    // weight prep + input pack
    prep_w_f16<32> <<<(32*32*9  + 255)/256, 256>>>(w_in, dWin);
    prep_w_f16<128><<<(32*128*9 + 255)/256, 256>>>(w2, dW2);
    prep_w_f16<128><<<(32*128*9 + 255)/256, 256>>>(w3, dW3);
    pack_x_kernel<<<Bn*16*HW/4/256, 256>>>(x, dXP);

    // 1. conv_in: packed x -> packed bufA
    conv_f16_kernel<16,2,0><<<296, 256, SMEMC>>>(dXP, (const uint32_t*)dWin, dA, nullptr);
    // 2. irnn1: bufA -> bufB
    hscan_kernel<<<256, 256>>>(dA, dB, i1w, i1b);
    wscan_kernel<<<128, 256>>>(dA, dB, i1w, i1b);
    // 3. conv2: bufB -> packed bufA
    conv_f16_kernel<64,8,0><<<296, 256, SMEMC>>>(dB, (const uint32_t*)dW2, dA, nullptr);
    // 4. irnn2: bufA -> bufB
    hscan_kernel<<<256, 256>>>(dA, dB, i2w, i2b);
    wscan_kernel<<<128, 256>>>(dA, dB, i2w, i2b);
    // 5. conv3 + relu + conv_out + sigmoid: bufB -> d_out
    conv_f16_kernel<64,8,2><<<296, 256, SMEMC>>>(dB, (const uint32_t*)dW3, out, w_out);
}

// round 10
// speedup vs baseline: 11.6605x; 1.0777x over previous
#include <cuda_runtime.h>
#include <cuda_fp16.h>
#include <math.h>
#include <stdint.h>

#define Bn 8
#define Cc 32
#define Hh 256
#define Ww 256
#define HW (Hh*Ww)

// ---------------------------------------------------------------------------
// Scratch buffers (allocation-free rule: __device__ globals). Inter-kernel
// tensors are half2-packed pair planes: plane (b*NP + c/2) = channels (c,c+1).
// ---------------------------------------------------------------------------
__device__ __align__(16) uint32_t g_xpk[Bn*16*HW];    //  33 MB: packed x
__device__ __align__(16) uint32_t g_bufA[Bn*16*HW];   //  33 MB: conv outputs (16 pair planes)
__device__ __align__(16) uint32_t g_bufB[Bn*64*HW];   // 134 MB: IRNN outputs (64 pair planes)
// fp16 weights: [ch][tap(9)][co(32)][slot(8) x half2]
__device__ __align__(16) __half g_win_h[2*9*32*16];   // CIN=32  (2 chunks)
__device__ __align__(16) __half g_w2_h[8*9*32*16];    // CIN=128 (8 chunks)
__device__ __align__(16) __half g_w3_h[8*9*32*16];

__device__ __forceinline__ uint32_t smem_u32(const void* p) {
    uint32_t a;
    asm("{ .reg .u64 t; cvta.to.shared.u64 t, %1; cvt.u32.u64 %0, t; }" : "=r"(a) : "l"(p));
    return a;
}
__device__ __forceinline__ void cp16(uint32_t dst, const void* src, bool pred) {
    int sz = pred ? 16 : 0;
    asm volatile("cp.async.cg.shared.global [%0], [%1], 16, %2;"
                 :: "r"(dst), "l"(src), "r"(sz) : "memory");
}
__device__ __forceinline__ void cp_commit() {
    asm volatile("cp.async.commit_group;" ::: "memory");
}
template<int N>
__device__ __forceinline__ void cp_wait() {
    asm volatile("cp.async.wait_group %0;" :: "n"(N) : "memory");
}
__device__ __forceinline__ uint32_t packh2(float a, float b) {
    __half2 h = __floats2half2_rn(a, b);
    return *reinterpret_cast<uint32_t*>(&h);
}
__device__ __forceinline__ float2 unpackh2(uint32_t w) {
    __half2 h = *reinterpret_cast<__half2*>(&w);
    return __half22float2(h);
}

// ---------------------------------------------------------------------------
// Pack x (fp32 NCHW) -> half2 pair planes. One thread = 4 pixels.
// ---------------------------------------------------------------------------
__global__ void __launch_bounds__(256) pack_x_kernel(
    const float* __restrict__ x, uint32_t* __restrict__ xp)
{
    int idx = blockIdx.x * 256 + threadIdx.x;
    int p4 = idx & (HW/4 - 1);
    int pl = idx >> 14;
    const float* g0 = x + (size_t)pl*2*HW + p4*4;
    const float* g1 = g0 + HW;
    float4 v0 = *(const float4*)g0;
    float4 v1 = *(const float4*)g1;
    uint4 d;
    d.x = packh2(v0.x, v1.x);
    d.y = packh2(v0.y, v1.y);
    d.z = packh2(v0.z, v1.z);
    d.w = packh2(v0.w, v1.w);
    *(uint4*)(xp + (size_t)pl*HW + p4*4) = d;
}

// ---------------------------------------------------------------------------
// Weight prep fp16: ci -> chunk ch=ci>>4, k=ci&15, pair p=k>>1,
// slot s=(p<4)?2p:2(p-4)+1 so a uint2 at 2*c4 yields (b0,b1) fragments.
// ---------------------------------------------------------------------------
template<int CIN>
__global__ void prep_w_f16(const float* __restrict__ w, __half* __restrict__ wbuf)
{
    int idx = blockIdx.x * 256 + threadIdx.x;
    if (idx >= 32*CIN*9) return;
    int dx = idx % 3;
    int dy = (idx / 3) % 3;
    int ci = (idx / 9) % CIN;
    int co = idx / (9*CIN);
    int ch = ci >> 4, k = ci & 15;
    int p = k >> 1, hf = k & 1;
    int s = (p < 4) ? 2*p : 2*(p - 4) + 1;
    wbuf[(((ch*9 + dy*3 + dx)*32 + co)*8 + s)*2 + hf] = __float2half_rn(w[idx]);
}

// ---------------------------------------------------------------------------
// fp16 mma m16n8k16 implicit-GEMM 3x3 conv, pad=1, Cout=32.
// CTA: 256 thr (8 warps), tile 64x4 = 256 px (mb=2) -> 3 CTAs/SM, 24 warps.
// Input: NPL pair planes per batch, chunk = 8 pair planes (16 ch), NCH chunks.
// 3-buffer cp.async ring (2-deep prefetch).
// OUTMODE 0: packed half2 store (16 pair planes). 2: relu+1x1+sigmoid fp32.
// ---------------------------------------------------------------------------
template<int NPL, int NCH, int OUTMODE>
__global__ void __launch_bounds__(256, 3) conv_f16_kernel(
    const uint32_t* __restrict__ in, const uint32_t* __restrict__ wbuf,
    void* __restrict__ outp, const float* __restrict__ w_out)
{
    constexpr int INW = 6*8*72;        // 3456 words per input buffer
    constexpr int WW  = 9*32*8;        // 2304 words per weight slice
    extern __shared__ float sm[];
    float* s_in[3] = { sm, sm + INW, sm + 2*INW };
    float* s_w[3]  = { sm + 3*INW, sm + 3*INW + WW, sm + 3*INW + 2*WW };
    const uint32_t s_in_u[3] = { smem_u32(s_in[0]), smem_u32(s_in[1]), smem_u32(s_in[2]) };
    const uint32_t s_w_u[3]  = { smem_u32(s_w[0]),  smem_u32(s_w[1]),  smem_u32(s_w[2])  };

    const int tid = threadIdx.x;
    const int lane = tid & 31;
    const int wrp = tid >> 5;
    const int r4 = lane >> 2, c4 = lane & 3;
    const int ywarp = wrp >> 1;          // 0..3
    const int xwarp = (wrp & 1) * 32;    // 0 or 32

    float wo0[4], wo1[4];
    if (OUTMODE == 2) {
#pragma unroll
        for (int nb = 0; nb < 4; nb++) {
            wo0[nb] = __ldg(w_out + nb*8 + c4*2);
            wo1[nb] = __ldg(w_out + nb*8 + c4*2 + 1);
        }
    }

    for (int tg = blockIdx.x; tg < 2048; tg += gridDim.x) {
        const int b  = tg >> 8;
        const int ty = (tg >> 2) & 63;
        const int tx = tg & 3;
        const int x0 = tx*64, y0 = ty*4;

        auto STAGE = [&](int ch) {
            const int bufi = ch % 3;
            const uint32_t* base = in + (size_t)(b*NPL + ch*8)*HW;
            // input: 6 iy x 8 planes x 18 float4 = 864 tasks
#pragma unroll
            for (int k = 0; k < 4; k++) {
                int t = tid + k*256;
                if (t < 864) {
                    int iy = t / 144;
                    int r  = t - iy*144;
                    int cpl = r / 18;
                    int f4 = r - cpl*18;
                    int gy = y0 - 1 + iy;
                    int gxs = x0 - 4 + f4*4;
                    bool pred = ((unsigned)gy < 256u) && ((unsigned)gxs <= 252u);
                    const uint32_t* src = base + (size_t)cpl*HW + (pred ? (gy*256 + gxs) : 0);
                    cp16(s_in_u[bufi] + (((iy*8 + cpl)*72 + f4*4) << 2), src, pred);
                }
            }
            const uint32_t* wsrc = wbuf + (size_t)ch*WW;
#pragma unroll
            for (int k = 0; k < 3; k++) {
                int t = tid + k*256;
                if (t < 576) cp16(s_w_u[bufi] + (t << 4), wsrc + t*4, true);
            }
            cp_commit();
        };

        float acc[2][4][4];
#pragma unroll
        for (int mb = 0; mb < 2; mb++)
#pragma unroll
            for (int nb = 0; nb < 4; nb++)
#pragma unroll
                for (int q = 0; q < 4; q++) acc[mb][nb][q] = 0.f;

        STAGE(0);
        if (NCH > 1) STAGE(1);

        for (int ch = 0; ch < NCH; ch++) {
            if (ch == NCH - 1) cp_wait<0>(); else cp_wait<1>();
            __syncthreads();
            if (ch + 2 < NCH) STAGE(ch + 2);

            const uint32_t* bufI = (const uint32_t*)s_in[ch % 3];
            const uint32_t* bw   = (const uint32_t*)s_w[ch % 3];
#pragma unroll
            for (int dy = 0; dy < 3; dy++)
#pragma unroll
            for (int dx = 0; dx < 3; dx++) {
                const int tap = dy*3 + dx;
                uint32_t a[2][4];
#pragma unroll
                for (int mb = 0; mb < 2; mb++) {
                    int iy = ywarp + dy;
                    int sx = xwarp + mb*16 + r4 + dx + 3;
                    int b0 = (iy*8 + c4)*72 + sx;
                    a[mb][0] = bufI[b0];
                    a[mb][1] = bufI[b0 + 8];
                    a[mb][2] = bufI[b0 + 4*72];
                    a[mb][3] = bufI[b0 + 4*72 + 8];
                }
#pragma unroll
                for (int nb = 0; nb < 4; nb++) {
                    uint2 bb = *(const uint2*)&bw[((tap*32 + nb*8 + r4) << 3) + c4*2];
#pragma unroll
                    for (int mb = 0; mb < 2; mb++) {
                        asm("mma.sync.aligned.m16n8k16.row.col.f32.f16.f16.f32 "
                            "{%0,%1,%2,%3}, {%4,%5,%6,%7}, {%8,%9}, {%0,%1,%2,%3};"
                            : "+f"(acc[mb][nb][0]), "+f"(acc[mb][nb][1]),
                              "+f"(acc[mb][nb][2]), "+f"(acc[mb][nb][3])
                            : "r"(a[mb][0]), "r"(a[mb][1]), "r"(a[mb][2]), "r"(a[mb][3]),
                              "r"(bb.x), "r"(bb.y));
                    }
                }
            }
        }

        if (OUTMODE == 2) {
            float* outO = (float*)outp + (size_t)b*HW + (y0 + ywarp)*256 + x0;
#pragma unroll
            for (int mb = 0; mb < 2; mb++) {
                int px = xwarp + mb*16 + r4;
                float pp = 0.f, pq = 0.f;
#pragma unroll
                for (int nb = 0; nb < 4; nb++) {
                    pp = fmaf(wo0[nb], fmaxf(acc[mb][nb][0], 0.f), pp);
                    pp = fmaf(wo1[nb], fmaxf(acc[mb][nb][1], 0.f), pp);
                    pq = fmaf(wo0[nb], fmaxf(acc[mb][nb][2], 0.f), pq);
                    pq = fmaf(wo1[nb], fmaxf(acc[mb][nb][3], 0.f), pq);
                }
                pp += __shfl_xor_sync(0xFFFFFFFFu, pp, 1);
                pp += __shfl_xor_sync(0xFFFFFFFFu, pp, 2);
                pq += __shfl_xor_sync(0xFFFFFFFFu, pq, 1);
                pq += __shfl_xor_sync(0xFFFFFFFFu, pq, 2);
                if (c4 == 0) {
                    outO[px]     = 1.f / (1.f + expf(-pp));
                    outO[px + 8] = 1.f / (1.f + expf(-pq));
                }
            }
        } else {
            uint32_t* outP = (uint32_t*)outp;
#pragma unroll
            for (int mb = 0; mb < 2; mb++) {
                int px = xwarp + mb*16 + r4;
#pragma unroll
                for (int nb = 0; nb < 4; nb++) {
                    uint32_t* orow = outP + (size_t)(b*16 + nb*4 + c4)*HW
                                   + (y0 + ywarp)*256 + x0 + px;
                    orow[0] = packh2(acc[mb][nb][0], acc[mb][nb][1]);
                    orow[8] = packh2(acc[mb][nb][2], acc[mb][nb][3]);
                }
            }
        }
        __syncthreads();   // guard buffer ring across grid-stride tiles
    }
}

// ---------------------------------------------------------------------------
// Fused IRNN scans: blocks 0..255 = H-direction (down/up), 256..383 =
// W-direction (right/left). H and W write disjoint bufB planes; no deps.
// ---------------------------------------------------------------------------
__global__ void __launch_bounds__(256) scan_kernel(
    const uint32_t* __restrict__ in, uint32_t* __restrict__ outp,
    const float* __restrict__ wp, const float* __restrict__ bp)
{
    __shared__ uint32_t xs[256*33];
    int blk = blockIdx.x;

    if (blk < 256) {
        // ---- H scans: (dir, b, cp), 256 thr = columns ----
        int d = blk >> 7;              // 0 = down, 1 = up
        int n = blk & 127;
        int b = n >> 4, cp = n & 15;
        int w = threadIdx.x;
        const uint32_t* g = in + (size_t)(b*16 + cp)*HW + w;

        if (d == 0) {                  // down (dir 2)
            uint32_t* gd = outp + (size_t)(b*64 + 32 + cp)*HW + w;
            float wc0 = wp[64 + 2*cp], bc0 = bp[64 + 2*cp];
            float wc1 = wp[64 + 2*cp + 1], bc1 = bp[64 + 2*cp + 1];
            float2 v = unpackh2(g[0]);
            float h0 = v.x, h1 = v.y;
            gd[0] = packh2(h0, h1);
#pragma unroll 8
            for (int i = 1; i < Hh; i++) {
                float2 x = unpackh2(g[i*Ww]);
                h0 = fmaxf(fmaf(wc0, h0, x.x + bc0), 0.f);
                h1 = fmaxf(fmaf(wc1, h1, x.y + bc1), 0.f);
                gd[i*Ww] = packh2(h0, h1);
            }
        } else {                       // up (dir 0)
            uint32_t* gu = outp + (size_t)(b*64 + cp)*HW + w;
            float wc0 = wp[2*cp], bc0 = bp[2*cp];
            float wc1 = wp[2*cp + 1], bc1 = bp[2*cp + 1];
            float2 v = unpackh2(g[(Hh-1)*Ww]);
            float h0 = v.x, h1 = v.y;
            gu[(Hh-1)*Ww] = packh2(h0, h1);
#pragma unroll 8
            for (int i = Hh - 2; i >= 0; i--) {
                float2 x = unpackh2(g[i*Ww]);
                h0 = fmaxf(fmaf(wc0, h0, x.x + bc0), 0.f);
                h1 = fmaxf(fmaf(wc1, h1, x.y + bc1), 0.f);
                gu[i*Ww] = packh2(h0, h1);
            }
        }
        return;
    }

    // ---- W scans: block per (b,cp), 256 thr = rows; smem tile stride 33 ----
    int n = blk - 256;
    int b = n >> 4, cp = n & 15;
    int t = threadIdx.x;
    const uint32_t* g = in + (size_t)(b*16 + cp)*HW;
    uint32_t* gr = outp + (size_t)(b*64 + 16 + cp)*HW;   // right (dir 1)
    uint32_t* gl = outp + (size_t)(b*64 + 48 + cp)*HW;   // left  (dir 3)

#pragma unroll 1
    for (int pass = 0; pass < 2; pass++) {
        const bool rightP = (pass == 0);
        float wc0 = wp[(rightP ? 32 : 96) + 2*cp], bc0 = bp[(rightP ? 32 : 96) + 2*cp];
        float wc1 = wp[(rightP ? 32 : 96) + 2*cp + 1], bc1 = bp[(rightP ? 32 : 96) + 2*cp + 1];
        uint32_t* go = rightP ? gr : gl;
        float h0 = 0.f, h1 = 0.f;
        for (int s = 0; s < 8; s++) {
            int cx = rightP ? s : 7 - s;
#pragma unroll
            for (int k = 0; k < 8; k++) {
                int i4 = t + k*256;
                int row = i4 >> 3, f4 = i4 & 7;
                uint4 v = *(const uint4*)(g + row*256 + cx*32 + f4*4);
                uint32_t* d = &xs[row*33 + f4*4];
                d[0] = v.x; d[1] = v.y; d[2] = v.z; d[3] = v.w;
            }
            __syncthreads();
            uint32_t* xr = &xs[t*33];
            if (rightP) {
                { float2 x = unpackh2(xr[0]);
                  if (s == 0) { h0 = x.x; h1 = x.y; }
                  else { h0 = fmaxf(fmaf(wc0, h0, x.x + bc0), 0.f);
                         h1 = fmaxf(fmaf(wc1, h1, x.y + bc1), 0.f); }
                  xr[0] = packh2(h0, h1); }
#pragma unroll
                for (int j = 1; j < 32; j++) {
                    float2 x = unpackh2(xr[j]);
                    h0 = fmaxf(fmaf(wc0, h0, x.x + bc0), 0.f);
                    h1 = fmaxf(fmaf(wc1, h1, x.y + bc1), 0.f);
                    xr[j] = packh2(h0, h1);
                }
            } else {
                { float2 x = unpackh2(xr[31]);
                  if (s == 0) { h0 = x.x; h1 = x.y; }
                  else { h0 = fmaxf(fmaf(wc0, h0, x.x + bc0), 0.f);
                         h1 = fmaxf(fmaf(wc1, h1, x.y + bc1), 0.f); }
                  xr[31] = packh2(h0, h1); }
#pragma unroll
                for (int j = 30; j >= 0; j--) {
                    float2 x = unpackh2(xr[j]);
                    h0 = fmaxf(fmaf(wc0, h0, x.x + bc0), 0.f);
                    h1 = fmaxf(fmaf(wc1, h1, x.y + bc1), 0.f);
                    xr[j] = packh2(h0, h1);
                }
            }
            __syncthreads();
#pragma unroll
            for (int k = 0; k < 8; k++) {
                int i4 = t + k*256;
                int row = i4 >> 3, f4 = i4 & 7;
                uint32_t* sp = &xs[row*33 + f4*4];
                *(uint4*)(go + row*256 + cx*32 + f4*4)
                    = make_uint4(sp[0], sp[1], sp[2], sp[3]);
            }
            __syncthreads();
        }
    }
}

// ---------------------------------------------------------------------------
extern "C" void kernel_launch(void* const* d_in, const int* in_sizes, int n_in,
                              void* d_out, int out_size)
{
    const float* x     = (const float*)d_in[0];
    const float* w_in  = (const float*)d_in[1];
    const float* w2    = (const float*)d_in[2];
    const float* w3    = (const float*)d_in[3];
    const float* w_out = (const float*)d_in[4];
    const float* i1w   = (const float*)d_in[5];
    const float* i1b   = (const float*)d_in[6];
    const float* i2w   = (const float*)d_in[7];
    const float* i2b   = (const float*)d_in[8];
    float* out = (float*)d_out;

    uint32_t *dXP, *dA, *dB;
    __half *dWin, *dW2, *dW3;
    cudaGetSymbolAddress((void**)&dXP, g_xpk);
    cudaGetSymbolAddress((void**)&dA, g_bufA);
    cudaGetSymbolAddress((void**)&dB, g_bufB);
    cudaGetSymbolAddress((void**)&dWin, g_win_h);
    cudaGetSymbolAddress((void**)&dW2, g_w2_h);
    cudaGetSymbolAddress((void**)&dW3, g_w3_h);

    const int SMEMC = (3*3456 + 3*2304) * 4;   // 69120 B -> 3 CTAs/SM
    cudaFuncSetAttribute((const void*)conv_f16_kernel<16,2,0>,
                         cudaFuncAttributeMaxDynamicSharedMemorySize, SMEMC);
    cudaFuncSetAttribute((const void*)conv_f16_kernel<64,8,0>,
                         cudaFuncAttributeMaxDynamicSharedMemorySize, SMEMC);
    cudaFuncSetAttribute((const void*)conv_f16_kernel<64,8,2>,
                         cudaFuncAttributeMaxDynamicSharedMemorySize, SMEMC);

    // weight prep + input pack
    prep_w_f16<32> <<<(32*32*9  + 255)/256, 256>>>(w_in, dWin);
    prep_w_f16<128><<<(32*128*9 + 255)/256, 256>>>(w2, dW2);
    prep_w_f16<128><<<(32*128*9 + 255)/256, 256>>>(w3, dW3);
    pack_x_kernel<<<Bn*16*HW/4/256, 256>>>(x, dXP);

    // 1. conv_in: packed x -> packed bufA
    conv_f16_kernel<16,2,0><<<444, 256, SMEMC>>>(dXP, (const uint32_t*)dWin, dA, nullptr);
    // 2. irnn1: bufA -> bufB (H + W scans fused, disjoint outputs)
    scan_kernel<<<384, 256>>>(dA, dB, i1w, i1b);
    // 3. conv2: bufB -> packed bufA
    conv_f16_kernel<64,8,0><<<444, 256, SMEMC>>>(dB, (const uint32_t*)dW2, dA, nullptr);
    // 4. irnn2: bufA -> bufB
    scan_kernel<<<384, 256>>>(dA, dB, i2w, i2b);
    // 5. conv3 + relu + conv_out + sigmoid: bufB -> d_out
    conv_f16_kernel<64,8,2><<<444, 256, SMEMC>>>(dB, (const uint32_t*)dW3, out, w_out);
}

// round 11
// speedup vs baseline: 12.7178x; 1.0907x over previous
#include <cuda_runtime.h>
#include <cuda_fp16.h>
#include <math.h>
#include <stdint.h>

#define Bn 8
#define Cc 32
#define Hh 256
#define Ww 256
#define HW (Hh*Ww)

// ---------------------------------------------------------------------------
// Scratch buffers (allocation-free rule: __device__ globals). Inter-kernel
// tensors are half2-packed pair planes: plane (b*NP + c/2) = channels (c,c+1).
// ---------------------------------------------------------------------------
__device__ __align__(16) uint32_t g_xpk[Bn*16*HW];    //  33 MB: packed x
__device__ __align__(16) uint32_t g_bufA[Bn*16*HW];   //  33 MB: conv outputs (16 pair planes)
__device__ __align__(16) uint32_t g_bufB[Bn*64*HW];   // 134 MB: IRNN outputs (64 pair planes)
// fp16 weights: [ch][tap(9)][co(32)][slot(8) x half2]
__device__ __align__(16) __half g_win_h[2*9*32*16];   // CIN=32  (2 chunks)
__device__ __align__(16) __half g_w2_h[8*9*32*16];    // CIN=128 (8 chunks)
__device__ __align__(16) __half g_w3_h[8*9*32*16];

__device__ __forceinline__ uint32_t smem_u32(const void* p) {
    uint32_t a;
    asm("{ .reg .u64 t; cvta.to.shared.u64 t, %1; cvt.u32.u64 %0, t; }" : "=r"(a) : "l"(p));
    return a;
}
__device__ __forceinline__ void cp16(uint32_t dst, const void* src, bool pred) {
    int sz = pred ? 16 : 0;
    asm volatile("cp.async.cg.shared.global [%0], [%1], 16, %2;"
                 :: "r"(dst), "l"(src), "r"(sz) : "memory");
}
__device__ __forceinline__ void cp_commit() {
    asm volatile("cp.async.commit_group;" ::: "memory");
}
template<int N>
__device__ __forceinline__ void cp_wait() {
    asm volatile("cp.async.wait_group %0;" :: "n"(N) : "memory");
}
__device__ __forceinline__ uint32_t packh2(float a, float b) {
    __half2 h = __floats2half2_rn(a, b);
    return *reinterpret_cast<uint32_t*>(&h);
}
__device__ __forceinline__ float2 unpackh2(uint32_t w) {
    __half2 h = *reinterpret_cast<__half2*>(&w);
    return __half22float2(h);
}

// ---------------------------------------------------------------------------
// Pack x (fp32 NCHW) -> half2 pair planes. One thread = 4 pixels.
// ---------------------------------------------------------------------------
__global__ void __launch_bounds__(256) pack_x_kernel(
    const float* __restrict__ x, uint32_t* __restrict__ xp)
{
    int idx = blockIdx.x * 256 + threadIdx.x;
    int p4 = idx & (HW/4 - 1);
    int pl = idx >> 14;
    const float* g0 = x + (size_t)pl*2*HW + p4*4;
    const float* g1 = g0 + HW;
    float4 v0 = *(const float4*)g0;
    float4 v1 = *(const float4*)g1;
    uint4 d;
    d.x = packh2(v0.x, v1.x);
    d.y = packh2(v0.y, v1.y);
    d.z = packh2(v0.z, v1.z);
    d.w = packh2(v0.w, v1.w);
    *(uint4*)(xp + (size_t)pl*HW + p4*4) = d;
}

// ---------------------------------------------------------------------------
// Weight prep fp16: ci -> chunk ch=ci>>4, k=ci&15, pair p=k>>1,
// slot s=(p<4)?2p:2(p-4)+1 so a uint2 at 2*c4 yields (b0,b1) fragments.
// ---------------------------------------------------------------------------
template<int CIN>
__global__ void prep_w_f16(const float* __restrict__ w, __half* __restrict__ wbuf)
{
    int idx = blockIdx.x * 256 + threadIdx.x;
    if (idx >= 32*CIN*9) return;
    int dx = idx % 3;
    int dy = (idx / 3) % 3;
    int ci = (idx / 9) % CIN;
    int co = idx / (9*CIN);
    int ch = ci >> 4, k = ci & 15;
    int p = k >> 1, hf = k & 1;
    int s = (p < 4) ? 2*p : 2*(p - 4) + 1;
    wbuf[(((ch*9 + dy*3 + dx)*32 + co)*8 + s)*2 + hf] = __float2half_rn(w[idx]);
}

// ---------------------------------------------------------------------------
// fp16 mma m16n8k16 implicit-GEMM 3x3 conv, pad=1, Cout=32.
// CTA: 256 thr (8 warps), tile 128x4 = 512 px (mb=4 -> 192 B smem per mma).
// Tiles [tg0, tg1) processed grid-stride (per-half-batch chaining for L2).
// OUTMODE 0: packed half2 store (16 pair planes). 2: relu+1x1+sigmoid fp32.
// ---------------------------------------------------------------------------
template<int NPL, int NCH, int OUTMODE>
__global__ void __launch_bounds__(256, 2) conv_f16_kernel(
    const uint32_t* __restrict__ in, const uint32_t* __restrict__ wbuf,
    void* __restrict__ outp, const float* __restrict__ w_out,
    int tg0, int tg1)
{
    constexpr int INW = 6*8*136;       // 6528 words per input buffer
    constexpr int WW  = 9*32*8;        // 2304 words per weight slice
    extern __shared__ float sm[];
    float* s_in[3] = { sm, sm + INW, sm + 2*INW };
    float* s_w[3]  = { sm + 3*INW, sm + 3*INW + WW, sm + 3*INW + 2*WW };
    const uint32_t s_in_u[3] = { smem_u32(s_in[0]), smem_u32(s_in[1]), smem_u32(s_in[2]) };
    const uint32_t s_w_u[3]  = { smem_u32(s_w[0]),  smem_u32(s_w[1]),  smem_u32(s_w[2])  };

    const int tid = threadIdx.x;
    const int lane = tid & 31;
    const int wrp = tid >> 5;
    const int r4 = lane >> 2, c4 = lane & 3;
    const int ywarp = wrp >> 1;          // 0..3
    const int xwarp = (wrp & 1) * 64;    // 0 or 64

    float wo0[4], wo1[4];
    if (OUTMODE == 2) {
#pragma unroll
        for (int nb = 0; nb < 4; nb++) {
            wo0[nb] = __ldg(w_out + nb*8 + c4*2);
            wo1[nb] = __ldg(w_out + nb*8 + c4*2 + 1);
        }
    }

    for (int tg = tg0 + blockIdx.x; tg < tg1; tg += gridDim.x) {
        const int b  = tg >> 7;
        const int ty = (tg >> 1) & 63;
        const int tx = tg & 1;
        const int x0 = tx*128, y0 = ty*4;

        auto STAGE = [&](int ch) {
            const int bufi = ch % 3;
            const uint32_t* base = in + (size_t)(b*NPL + ch*8)*HW;
#pragma unroll
            for (int k = 0; k < 7; k++) {
                int t = tid + k*256;
                if (t < 1632) {
                    int iy = t / 272;
                    int r  = t - iy*272;
                    int cpl = r / 34;
                    int f4 = r - cpl*34;
                    int gy = y0 - 1 + iy;
                    int gxs = x0 - 4 + f4*4;
                    bool pred = ((unsigned)gy < 256u) && ((unsigned)gxs <= 252u);
                    const uint32_t* src = base + (size_t)cpl*HW + (pred ? (gy*256 + gxs) : 0);
                    cp16(s_in_u[bufi] + (((iy*8 + cpl)*136 + f4*4) << 2), src, pred);
                }
            }
            const uint32_t* wsrc = wbuf + (size_t)ch*WW;
#pragma unroll
            for (int k = 0; k < 3; k++) {
                int t = tid + k*256;
                if (t < 576) cp16(s_w_u[bufi] + (t << 4), wsrc + t*4, true);
            }
            cp_commit();
        };

        float acc[4][4][4];
#pragma unroll
        for (int mb = 0; mb < 4; mb++)
#pragma unroll
            for (int nb = 0; nb < 4; nb++)
#pragma unroll
                for (int q = 0; q < 4; q++) acc[mb][nb][q] = 0.f;

        STAGE(0);
        if (NCH > 1) STAGE(1);

        for (int ch = 0; ch < NCH; ch++) {
            if (ch == NCH - 1) cp_wait<0>(); else cp_wait<1>();
            __syncthreads();
            if (ch + 2 < NCH) STAGE(ch + 2);

            const uint32_t* bufI = (const uint32_t*)s_in[ch % 3];
            const uint32_t* bw   = (const uint32_t*)s_w[ch % 3];
#pragma unroll
            for (int dy = 0; dy < 3; dy++)
#pragma unroll
            for (int dx = 0; dx < 3; dx++) {
                const int tap = dy*3 + dx;
                uint32_t a[4][4];
#pragma unroll
                for (int mb = 0; mb < 4; mb++) {
                    int iy = ywarp + dy;
                    int sx = xwarp + mb*16 + r4 + dx + 3;
                    int b0 = (iy*8 + c4)*136 + sx;
                    a[mb][0] = bufI[b0];
                    a[mb][1] = bufI[b0 + 8];
                    a[mb][2] = bufI[b0 + 4*136];
                    a[mb][3] = bufI[b0 + 4*136 + 8];
                }
#pragma unroll
                for (int nb = 0; nb < 4; nb++) {
                    uint2 bb = *(const uint2*)&bw[((tap*32 + nb*8 + r4) << 3) + c4*2];
#pragma unroll
                    for (int mb = 0; mb < 4; mb++) {
                        asm("mma.sync.aligned.m16n8k16.row.col.f32.f16.f16.f32 "
                            "{%0,%1,%2,%3}, {%4,%5,%6,%7}, {%8,%9}, {%0,%1,%2,%3};"
                            : "+f"(acc[mb][nb][0]), "+f"(acc[mb][nb][1]),
                              "+f"(acc[mb][nb][2]), "+f"(acc[mb][nb][3])
                            : "r"(a[mb][0]), "r"(a[mb][1]), "r"(a[mb][2]), "r"(a[mb][3]),
                              "r"(bb.x), "r"(bb.y));
                    }
                }
            }
        }

        if (OUTMODE == 2) {
            float* outO = (float*)outp + (size_t)b*HW + (y0 + ywarp)*256 + x0;
#pragma unroll
            for (int mb = 0; mb < 4; mb++) {
                int px = xwarp + mb*16 + r4;
                float pp = 0.f, pq = 0.f;
#pragma unroll
                for (int nb = 0; nb < 4; nb++) {
                    pp = fmaf(wo0[nb], fmaxf(acc[mb][nb][0], 0.f), pp);
                    pp = fmaf(wo1[nb], fmaxf(acc[mb][nb][1], 0.f), pp);
                    pq = fmaf(wo0[nb], fmaxf(acc[mb][nb][2], 0.f), pq);
                    pq = fmaf(wo1[nb], fmaxf(acc[mb][nb][3], 0.f), pq);
                }
                pp += __shfl_xor_sync(0xFFFFFFFFu, pp, 1);
                pp += __shfl_xor_sync(0xFFFFFFFFu, pp, 2);
                pq += __shfl_xor_sync(0xFFFFFFFFu, pq, 1);
                pq += __shfl_xor_sync(0xFFFFFFFFu, pq, 2);
                if (c4 == 0) {
                    outO[px]     = 1.f / (1.f + expf(-pp));
                    outO[px + 8] = 1.f / (1.f + expf(-pq));
                }
            }
        } else {
            uint32_t* outP = (uint32_t*)outp;
#pragma unroll
            for (int mb = 0; mb < 4; mb++) {
                int px = xwarp + mb*16 + r4;
#pragma unroll
                for (int nb = 0; nb < 4; nb++) {
                    uint32_t* orow = outP + (size_t)(b*16 + nb*4 + c4)*HW
                                   + (y0 + ywarp)*256 + x0 + px;
                    orow[0] = packh2(acc[mb][nb][0], acc[mb][nb][1]);
                    orow[8] = packh2(acc[mb][nb][2], acc[mb][nb][3]);
                }
            }
        }
        __syncthreads();   // guard buffer ring across grid-stride tiles
    }
}

// ---------------------------------------------------------------------------
// Fused IRNN scans for a 4-batch half: blocks [0,128) = H (dir,b,cp),
// [128,256) = W (dir,b,cp) — each W block does ONE direction.
// ---------------------------------------------------------------------------
__global__ void __launch_bounds__(256) scan_kernel(
    const uint32_t* __restrict__ in, uint32_t* __restrict__ outp,
    const float* __restrict__ wp, const float* __restrict__ bp, int b_base)
{
    __shared__ uint32_t xs[256*33];
    int blk = blockIdx.x;

    if (blk < 128) {
        // ---- H scans ----
        int d = blk >> 6;              // 0 = down, 1 = up
        int n = blk & 63;
        int b = b_base + (n >> 4), cp = n & 15;
        int w = threadIdx.x;
        const uint32_t* g = in + (size_t)(b*16 + cp)*HW + w;

        if (d == 0) {                  // down (dir 2)
            uint32_t* gd = outp + (size_t)(b*64 + 32 + cp)*HW + w;
            float wc0 = wp[64 + 2*cp], bc0 = bp[64 + 2*cp];
            float wc1 = wp[64 + 2*cp + 1], bc1 = bp[64 + 2*cp + 1];
            float2 v = unpackh2(g[0]);
            float h0 = v.x, h1 = v.y;
            gd[0] = packh2(h0, h1);
#pragma unroll 8
            for (int i = 1; i < Hh; i++) {
                float2 x = unpackh2(g[i*Ww]);
                h0 = fmaxf(fmaf(wc0, h0, x.x + bc0), 0.f);
                h1 = fmaxf(fmaf(wc1, h1, x.y + bc1), 0.f);
                gd[i*Ww] = packh2(h0, h1);
            }
        } else {                       // up (dir 0)
            uint32_t* gu = outp + (size_t)(b*64 + cp)*HW + w;
            float wc0 = wp[2*cp], bc0 = bp[2*cp];
            float wc1 = wp[2*cp + 1], bc1 = bp[2*cp + 1];
            float2 v = unpackh2(g[(Hh-1)*Ww]);
            float h0 = v.x, h1 = v.y;
            gu[(Hh-1)*Ww] = packh2(h0, h1);
#pragma unroll 8
            for (int i = Hh - 2; i >= 0; i--) {
                float2 x = unpackh2(g[i*Ww]);
                h0 = fmaxf(fmaf(wc0, h0, x.x + bc0), 0.f);
                h1 = fmaxf(fmaf(wc1, h1, x.y + bc1), 0.f);
                gu[i*Ww] = packh2(h0, h1);
            }
        }
        return;
    }

    // ---- W scans: one direction per block ----
    int m = blk - 128;
    int d = m >> 6;                    // 0 = right, 1 = left
    int n = m & 63;
    int b = b_base + (n >> 4), cp = n & 15;
    int t = threadIdx.x;
    const uint32_t* g = in + (size_t)(b*16 + cp)*HW;
    const bool rightP = (d == 0);
    uint32_t* go = outp + (size_t)(b*64 + (rightP ? 16 : 48) + cp)*HW;
    float wc0 = wp[(rightP ? 32 : 96) + 2*cp], bc0 = bp[(rightP ? 32 : 96) + 2*cp];
    float wc1 = wp[(rightP ? 32 : 96) + 2*cp + 1], bc1 = bp[(rightP ? 32 : 96) + 2*cp + 1];
    float h0 = 0.f, h1 = 0.f;

    for (int s = 0; s < 8; s++) {
        int cx = rightP ? s : 7 - s;
#pragma unroll
        for (int k = 0; k < 8; k++) {
            int i4 = t + k*256;
            int row = i4 >> 3, f4 = i4 & 7;
            uint4 v = *(const uint4*)(g + row*256 + cx*32 + f4*4);
            uint32_t* dd = &xs[row*33 + f4*4];
            dd[0] = v.x; dd[1] = v.y; dd[2] = v.z; dd[3] = v.w;
        }
        __syncthreads();
        uint32_t* xr = &xs[t*33];
        if (rightP) {
            { float2 x = unpackh2(xr[0]);
              if (s == 0) { h0 = x.x; h1 = x.y; }
              else { h0 = fmaxf(fmaf(wc0, h0, x.x + bc0), 0.f);
                     h1 = fmaxf(fmaf(wc1, h1, x.y + bc1), 0.f); }
              xr[0] = packh2(h0, h1); }
#pragma unroll
            for (int j = 1; j < 32; j++) {
                float2 x = unpackh2(xr[j]);
                h0 = fmaxf(fmaf(wc0, h0, x.x + bc0), 0.f);
                h1 = fmaxf(fmaf(wc1, h1, x.y + bc1), 0.f);
                xr[j] = packh2(h0, h1);
            }
        } else {
            { float2 x = unpackh2(xr[31]);
              if (s == 0) { h0 = x.x; h1 = x.y; }
              else { h0 = fmaxf(fmaf(wc0, h0, x.x + bc0), 0.f);
                     h1 = fmaxf(fmaf(wc1, h1, x.y + bc1), 0.f); }
              xr[31] = packh2(h0, h1); }
#pragma unroll
            for (int j = 30; j >= 0; j--) {
                float2 x = unpackh2(xr[j]);
                h0 = fmaxf(fmaf(wc0, h0, x.x + bc0), 0.f);
                h1 = fmaxf(fmaf(wc1, h1, x.y + bc1), 0.f);
                xr[j] = packh2(h0, h1);
            }
        }
        __syncthreads();
#pragma unroll
        for (int k = 0; k < 8; k++) {
            int i4 = t + k*256;
            int row = i4 >> 3, f4 = i4 & 7;
            uint32_t* sp = &xs[row*33 + f4*4];
            *(uint4*)(go + row*256 + cx*32 + f4*4)
                = make_uint4(sp[0], sp[1], sp[2], sp[3]);
        }
        __syncthreads();
    }
}

// ---------------------------------------------------------------------------
extern "C" void kernel_launch(void* const* d_in, const int* in_sizes, int n_in,
                              void* d_out, int out_size)
{
    const float* x     = (const float*)d_in[0];
    const float* w_in  = (const float*)d_in[1];
    const float* w2    = (const float*)d_in[2];
    const float* w3    = (const float*)d_in[3];
    const float* w_out = (const float*)d_in[4];
    const float* i1w   = (const float*)d_in[5];
    const float* i1b   = (const float*)d_in[6];
    const float* i2w   = (const float*)d_in[7];
    const float* i2b   = (const float*)d_in[8];
    float* out = (float*)d_out;

    uint32_t *dXP, *dA, *dB;
    __half *dWin, *dW2, *dW3;
    cudaGetSymbolAddress((void**)&dXP, g_xpk);
    cudaGetSymbolAddress((void**)&dA, g_bufA);
    cudaGetSymbolAddress((void**)&dB, g_bufB);
    cudaGetSymbolAddress((void**)&dWin, g_win_h);
    cudaGetSymbolAddress((void**)&dW2, g_w2_h);
    cudaGetSymbolAddress((void**)&dW3, g_w3_h);

    const int SMEMC = (3*6528 + 3*2304) * 4;   // 105984 B -> 2 CTAs/SM
    cudaFuncSetAttribute((const void*)conv_f16_kernel<16,2,0>,
                         cudaFuncAttributeMaxDynamicSharedMemorySize, SMEMC);
    cudaFuncSetAttribute((const void*)conv_f16_kernel<64,8,0>,
                         cudaFuncAttributeMaxDynamicSharedMemorySize, SMEMC);
    cudaFuncSetAttribute((const void*)conv_f16_kernel<64,8,2>,
                         cudaFuncAttributeMaxDynamicSharedMemorySize, SMEMC);

    // weight prep + input pack (whole batch)
    prep_w_f16<32> <<<(32*32*9  + 255)/256, 256>>>(w_in, dWin);
    prep_w_f16<128><<<(32*128*9 + 255)/256, 256>>>(w2, dW2);
    prep_w_f16<128><<<(32*128*9 + 255)/256, 256>>>(w3, dW3);
    pack_x_kernel<<<Bn*16*HW/4/256, 256>>>(x, dXP);

    // Per-half-batch chaining: each half's bufB slice (67 MB) stays L2-hot
    // between scan and the conv that consumes it.
    for (int h = 0; h < 2; h++) {
        int t0 = h*512, t1 = t0 + 512;      // conv tiles (128x4): 512 per half
        int b0 = h*4;
        // 1. conv_in: packed x -> packed bufA
        conv_f16_kernel<16,2,0><<<296, 256, SMEMC>>>(dXP, (const uint32_t*)dWin,
                                                     dA, nullptr, t0, t1);
        // 2. irnn1: bufA -> bufB
        scan_kernel<<<256, 256>>>(dA, dB, i1w, i1b, b0);
        // 3. conv2: bufB -> packed bufA
        conv_f16_kernel<64,8,0><<<296, 256, SMEMC>>>(dB, (const uint32_t*)dW2,
                                                     dA, nullptr, t0, t1);
        // 4. irnn2: bufA -> bufB
        scan_kernel<<<256, 256>>>(dA, dB, i2w, i2b, b0);
        // 5. conv3 + relu + conv_out + sigmoid: bufB -> d_out
        conv_f16_kernel<64,8,2><<<296, 256, SMEMC>>>(dB, (const uint32_t*)dW3,
                                                     out, w_out, t0, t1);
    }
}

// round 12
// speedup vs baseline: 12.8366x; 1.0093x over previous
#include <cuda_runtime.h>
#include <cuda_fp16.h>
#include <math.h>
#include <stdint.h>

#define Bn 8
#define Cc 32
#define Hh 256
#define Ww 256
#define HW (Hh*Ww)

// ---------------------------------------------------------------------------
// Scratch buffers (allocation-free rule: __device__ globals). Inter-kernel
// tensors are half2-packed pair planes: plane (b*NP + c/2) = channels (c,c+1).
// ---------------------------------------------------------------------------
__device__ __align__(16) uint32_t g_xpk[Bn*16*HW];    //  33 MB: packed x
__device__ __align__(16) uint32_t g_bufA[Bn*16*HW];   //  33 MB: conv outputs (16 pair planes)
__device__ __align__(16) uint32_t g_bufB[Bn*64*HW];   // 134 MB: IRNN outputs (64 pair planes)
__device__ int g_ctr[8];                               // conv tile pool counters
// fp16 weights: [ch][tap(9)][co(32)][slot(8) x half2]
__device__ __align__(16) __half g_win_h[2*9*32*16];   // CIN=32  (2 chunks)
__device__ __align__(16) __half g_w2_h[8*9*32*16];    // CIN=128 (8 chunks)
__device__ __align__(16) __half g_w3_h[8*9*32*16];

__device__ __forceinline__ uint32_t smem_u32(const void* p) {
    uint32_t a;
    asm("{ .reg .u64 t; cvta.to.shared.u64 t, %1; cvt.u32.u64 %0, t; }" : "=r"(a) : "l"(p));
    return a;
}
__device__ __forceinline__ void cp16(uint32_t dst, const void* src, bool pred) {
    int sz = pred ? 16 : 0;
    asm volatile("cp.async.cg.shared.global [%0], [%1], 16, %2;"
                 :: "r"(dst), "l"(src), "r"(sz) : "memory");
}
__device__ __forceinline__ void cp_commit() {
    asm volatile("cp.async.commit_group;" ::: "memory");
}
template<int N>
__device__ __forceinline__ void cp_wait() {
    asm volatile("cp.async.wait_group %0;" :: "n"(N) : "memory");
}
__device__ __forceinline__ uint32_t packh2(float a, float b) {
    __half2 h = __floats2half2_rn(a, b);
    return *reinterpret_cast<uint32_t*>(&h);
}
__device__ __forceinline__ float2 unpackh2(uint32_t w) {
    __half2 h = *reinterpret_cast<__half2*>(&w);
    return __half22float2(h);
}

// ---------------------------------------------------------------------------
// Pack x (fp32 NCHW) -> half2 pair planes. One thread = 4 pixels.
// ---------------------------------------------------------------------------
__global__ void __launch_bounds__(256) pack_x_kernel(
    const float* __restrict__ x, uint32_t* __restrict__ xp)
{
    int idx = blockIdx.x * 256 + threadIdx.x;
    int p4 = idx & (HW/4 - 1);
    int pl = idx >> 14;
    const float* g0 = x + (size_t)pl*2*HW + p4*4;
    const float* g1 = g0 + HW;
    float4 v0 = *(const float4*)g0;
    float4 v1 = *(const float4*)g1;
    uint4 d;
    d.x = packh2(v0.x, v1.x);
    d.y = packh2(v0.y, v1.y);
    d.z = packh2(v0.z, v1.z);
    d.w = packh2(v0.w, v1.w);
    *(uint4*)(xp + (size_t)pl*HW + p4*4) = d;
}

// ---------------------------------------------------------------------------
// Weight prep fp16: ci -> chunk ch=ci>>4, k=ci&15, pair p=k>>1,
// slot s=(p<4)?2p:2(p-4)+1 so a uint2 at 2*c4 yields (b0,b1) fragments.
// ---------------------------------------------------------------------------
template<int CIN>
__global__ void prep_w_f16(const float* __restrict__ w, __half* __restrict__ wbuf)
{
    int idx = blockIdx.x * 256 + threadIdx.x;
    if (idx >= 32*CIN*9) return;
    int dx = idx % 3;
    int dy = (idx / 3) % 3;
    int ci = (idx / 9) % CIN;
    int co = idx / (9*CIN);
    int ch = ci >> 4, k = ci & 15;
    int p = k >> 1, hf = k & 1;
    int s = (p < 4) ? 2*p : 2*(p - 4) + 1;
    wbuf[(((ch*9 + dy*3 + dx)*32 + co)*8 + s)*2 + hf] = __float2half_rn(w[idx]);
}

// ---------------------------------------------------------------------------
// Scan bodies (device functions). H: one block = (dir, b, cp), 256 thr =
// columns. W: one block = (dir, b, cp), 256 thr = rows, smem tile stride 33.
// ---------------------------------------------------------------------------
__device__ void scan_body(int blk, uint32_t* xs,
    const uint32_t* __restrict__ in, uint32_t* __restrict__ outp,
    const float* __restrict__ wp, const float* __restrict__ bp, int b_base)
{
    if (blk < 128) {
        int d = blk >> 6;              // 0 = down, 1 = up
        int n = blk & 63;
        int b = b_base + (n >> 4), cp = n & 15;
        int w = threadIdx.x;
        const uint32_t* g = in + (size_t)(b*16 + cp)*HW + w;

        if (d == 0) {                  // down (dir 2)
            uint32_t* gd = outp + (size_t)(b*64 + 32 + cp)*HW + w;
            float wc0 = wp[64 + 2*cp], bc0 = bp[64 + 2*cp];
            float wc1 = wp[64 + 2*cp + 1], bc1 = bp[64 + 2*cp + 1];
            float2 v = unpackh2(g[0]);
            float h0 = v.x, h1 = v.y;
            gd[0] = packh2(h0, h1);
#pragma unroll 8
            for (int i = 1; i < Hh; i++) {
                float2 x = unpackh2(g[i*Ww]);
                h0 = fmaxf(fmaf(wc0, h0, x.x + bc0), 0.f);
                h1 = fmaxf(fmaf(wc1, h1, x.y + bc1), 0.f);
                gd[i*Ww] = packh2(h0, h1);
            }
        } else {                       // up (dir 0)
            uint32_t* gu = outp + (size_t)(b*64 + cp)*HW + w;
            float wc0 = wp[2*cp], bc0 = bp[2*cp];
            float wc1 = wp[2*cp + 1], bc1 = bp[2*cp + 1];
            float2 v = unpackh2(g[(Hh-1)*Ww]);
            float h0 = v.x, h1 = v.y;
            gu[(Hh-1)*Ww] = packh2(h0, h1);
#pragma unroll 8
            for (int i = Hh - 2; i >= 0; i--) {
                float2 x = unpackh2(g[i*Ww]);
                h0 = fmaxf(fmaf(wc0, h0, x.x + bc0), 0.f);
                h1 = fmaxf(fmaf(wc1, h1, x.y + bc1), 0.f);
                gu[i*Ww] = packh2(h0, h1);
            }
        }
        return;
    }

    // ---- W scans: one direction per block ----
    int m = blk - 128;
    int d = m >> 6;                    // 0 = right, 1 = left
    int n = m & 63;
    int b = b_base + (n >> 4), cp = n & 15;
    int t = threadIdx.x;
    const uint32_t* g = in + (size_t)(b*16 + cp)*HW;
    const bool rightP = (d == 0);
    uint32_t* go = outp + (size_t)(b*64 + (rightP ? 16 : 48) + cp)*HW;
    float wc0 = wp[(rightP ? 32 : 96) + 2*cp], bc0 = bp[(rightP ? 32 : 96) + 2*cp];
    float wc1 = wp[(rightP ? 32 : 96) + 2*cp + 1], bc1 = bp[(rightP ? 32 : 96) + 2*cp + 1];
    float h0 = 0.f, h1 = 0.f;

    for (int s = 0; s < 8; s++) {
        int cx = rightP ? s : 7 - s;
#pragma unroll
        for (int k = 0; k < 8; k++) {
            int i4 = t + k*256;
            int row = i4 >> 3, f4 = i4 & 7;
            uint4 v = *(const uint4*)(g + row*256 + cx*32 + f4*4);
            uint32_t* dd = &xs[row*33 + f4*4];
            dd[0] = v.x; dd[1] = v.y; dd[2] = v.z; dd[3] = v.w;
        }
        __syncthreads();
        uint32_t* xr = &xs[t*33];
        if (rightP) {
            { float2 x = unpackh2(xr[0]);
              if (s == 0) { h0 = x.x; h1 = x.y; }
              else { h0 = fmaxf(fmaf(wc0, h0, x.x + bc0), 0.f);
                     h1 = fmaxf(fmaf(wc1, h1, x.y + bc1), 0.f); }
              xr[0] = packh2(h0, h1); }
#pragma unroll
            for (int j = 1; j < 32; j++) {
                float2 x = unpackh2(xr[j]);
                h0 = fmaxf(fmaf(wc0, h0, x.x + bc0), 0.f);
                h1 = fmaxf(fmaf(wc1, h1, x.y + bc1), 0.f);
                xr[j] = packh2(h0, h1);
            }
        } else {
            { float2 x = unpackh2(xr[31]);
              if (s == 0) { h0 = x.x; h1 = x.y; }
              else { h0 = fmaxf(fmaf(wc0, h0, x.x + bc0), 0.f);
                     h1 = fmaxf(fmaf(wc1, h1, x.y + bc1), 0.f); }
              xr[31] = packh2(h0, h1); }
#pragma unroll
            for (int j = 30; j >= 0; j--) {
                float2 x = unpackh2(xr[j]);
                h0 = fmaxf(fmaf(wc0, h0, x.x + bc0), 0.f);
                h1 = fmaxf(fmaf(wc1, h1, x.y + bc1), 0.f);
                xr[j] = packh2(h0, h1);
            }
        }
        __syncthreads();
#pragma unroll
        for (int k = 0; k < 8; k++) {
            int i4 = t + k*256;
            int row = i4 >> 3, f4 = i4 & 7;
            uint32_t* sp = &xs[row*33 + f4*4];
            *(uint4*)(go + row*256 + cx*32 + f4*4)
                = make_uint4(sp[0], sp[1], sp[2], sp[3]);
        }
        __syncthreads();
    }
}

// ---------------------------------------------------------------------------
// Fused kernel: blocks < nScan run one scan unit first (other half's IRNN),
// then ALL blocks drain the conv tile pool (atomic counter) for this half.
// Conv: fp16 mma m16n8k16 implicit-GEMM 3x3, tile 128x4, 3-buf cp.async ring.
// OUTMODE 0: packed half2 store. 2: relu + 1x1 conv_out + sigmoid (fp32).
// ---------------------------------------------------------------------------
template<int NPL, int NCH, int OUTMODE>
__global__ void __launch_bounds__(256, 2) fused_kernel(
    const uint32_t* __restrict__ in, const uint32_t* __restrict__ wbuf,
    void* __restrict__ outp, const float* __restrict__ w_out,
    int tileBase, int tileCount, int ctrIdx,
    const uint32_t* __restrict__ scanIn, uint32_t* __restrict__ scanOut,
    const float* __restrict__ swp, const float* __restrict__ sbp,
    int scanB0, int nScan)
{
    constexpr int INW = 6*8*136;       // 6528 words per input buffer
    constexpr int WW  = 9*32*8;        // 2304 words per weight slice
    extern __shared__ float sm[];
    __shared__ int s_tg;

    // ---- scan phase (first nScan blocks) ----
    if ((int)blockIdx.x < nScan)
        scan_body(blockIdx.x, (uint32_t*)sm, scanIn, scanOut, swp, sbp, scanB0);

    // ---- conv pool phase ----
    float* s_in[3] = { sm, sm + INW, sm + 2*INW };
    float* s_w[3]  = { sm + 3*INW, sm + 3*INW + WW, sm + 3*INW + 2*WW };
    const uint32_t s_in_u[3] = { smem_u32(s_in[0]), smem_u32(s_in[1]), smem_u32(s_in[2]) };
    const uint32_t s_w_u[3]  = { smem_u32(s_w[0]),  smem_u32(s_w[1]),  smem_u32(s_w[2])  };

    const int tid = threadIdx.x;
    const int lane = tid & 31;
    const int wrp = tid >> 5;
    const int r4 = lane >> 2, c4 = lane & 3;
    const int ywarp = wrp >> 1;          // 0..3
    const int xwarp = (wrp & 1) * 64;    // 0 or 64

    float wo0[4], wo1[4];
    if (OUTMODE == 2) {
#pragma unroll
        for (int nb = 0; nb < 4; nb++) {
            wo0[nb] = __ldg(w_out + nb*8 + c4*2);
            wo1[nb] = __ldg(w_out + nb*8 + c4*2 + 1);
        }
    }

    for (;;) {
        if (tid == 0) s_tg = atomicAdd(&g_ctr[ctrIdx], 1);
        __syncthreads();
        const int tpool = s_tg;
        __syncthreads();               // s_tg consumed before next fetch
        if (tpool >= tileCount) break;
        const int tg = tileBase + tpool;

        const int b  = tg >> 7;
        const int ty = (tg >> 1) & 63;
        const int tx = tg & 1;
        const int x0 = tx*128, y0 = ty*4;

        auto STAGE = [&](int ch) {
            const int bufi = ch % 3;
            const uint32_t* base = in + (size_t)(b*NPL + ch*8)*HW;
#pragma unroll
            for (int k = 0; k < 7; k++) {
                int t = tid + k*256;
                if (t < 1632) {
                    int iy = t / 272;
                    int r  = t - iy*272;
                    int cpl = r / 34;
                    int f4 = r - cpl*34;
                    int gy = y0 - 1 + iy;
                    int gxs = x0 - 4 + f4*4;
                    bool pred = ((unsigned)gy < 256u) && ((unsigned)gxs <= 252u);
                    const uint32_t* src = base + (size_t)cpl*HW + (pred ? (gy*256 + gxs) : 0);
                    cp16(s_in_u[bufi] + (((iy*8 + cpl)*136 + f4*4) << 2), src, pred);
                }
            }
            const uint32_t* wsrc = wbuf + (size_t)ch*WW;
#pragma unroll
            for (int k = 0; k < 3; k++) {
                int t = tid + k*256;
                if (t < 576) cp16(s_w_u[bufi] + (t << 4), wsrc + t*4, true);
            }
            cp_commit();
        };

        float acc[4][4][4];
#pragma unroll
        for (int mb = 0; mb < 4; mb++)
#pragma unroll
            for (int nb = 0; nb < 4; nb++)
#pragma unroll
                for (int q = 0; q < 4; q++) acc[mb][nb][q] = 0.f;

        STAGE(0);
        if (NCH > 1) STAGE(1);

        for (int ch = 0; ch < NCH; ch++) {
            if (ch == NCH - 1) cp_wait<0>(); else cp_wait<1>();
            __syncthreads();
            if (ch + 2 < NCH) STAGE(ch + 2);

            const uint32_t* bufI = (const uint32_t*)s_in[ch % 3];
            const uint32_t* bw   = (const uint32_t*)s_w[ch % 3];
#pragma unroll
            for (int dy = 0; dy < 3; dy++)
#pragma unroll
            for (int dx = 0; dx < 3; dx++) {
                const int tap = dy*3 + dx;
                uint32_t a[4][4];
#pragma unroll
                for (int mb = 0; mb < 4; mb++) {
                    int iy = ywarp + dy;
                    int sx = xwarp + mb*16 + r4 + dx + 3;
                    int b0 = (iy*8 + c4)*136 + sx;
                    a[mb][0] = bufI[b0];
                    a[mb][1] = bufI[b0 + 8];
                    a[mb][2] = bufI[b0 + 4*136];
                    a[mb][3] = bufI[b0 + 4*136 + 8];
                }
#pragma unroll
                for (int nb = 0; nb < 4; nb++) {
                    uint2 bb = *(const uint2*)&bw[((tap*32 + nb*8 + r4) << 3) + c4*2];
#pragma unroll
                    for (int mb = 0; mb < 4; mb++) {
                        asm("mma.sync.aligned.m16n8k16.row.col.f32.f16.f16.f32 "
                            "{%0,%1,%2,%3}, {%4,%5,%6,%7}, {%8,%9}, {%0,%1,%2,%3};"
                            : "+f"(acc[mb][nb][0]), "+f"(acc[mb][nb][1]),
                              "+f"(acc[mb][nb][2]), "+f"(acc[mb][nb][3])
                            : "r"(a[mb][0]), "r"(a[mb][1]), "r"(a[mb][2]), "r"(a[mb][3]),
                              "r"(bb.x), "r"(bb.y));
                    }
                }
            }
        }

        if (OUTMODE == 2) {
            float* outO = (float*)outp + (size_t)b*HW + (y0 + ywarp)*256 + x0;
#pragma unroll
            for (int mb = 0; mb < 4; mb++) {
                int px = xwarp + mb*16 + r4;
                float pp = 0.f, pq = 0.f;
#pragma unroll
                for (int nb = 0; nb < 4; nb++) {
                    pp = fmaf(wo0[nb], fmaxf(acc[mb][nb][0], 0.f), pp);
                    pp = fmaf(wo1[nb], fmaxf(acc[mb][nb][1], 0.f), pp);
                    pq = fmaf(wo0[nb], fmaxf(acc[mb][nb][2], 0.f), pq);
                    pq = fmaf(wo1[nb], fmaxf(acc[mb][nb][3], 0.f), pq);
                }
                pp += __shfl_xor_sync(0xFFFFFFFFu, pp, 1);
                pp += __shfl_xor_sync(0xFFFFFFFFu, pp, 2);
                pq += __shfl_xor_sync(0xFFFFFFFFu, pq, 1);
                pq += __shfl_xor_sync(0xFFFFFFFFu, pq, 2);
                if (c4 == 0) {
                    outO[px]     = 1.f / (1.f + expf(-pp));
                    outO[px + 8] = 1.f / (1.f + expf(-pq));
                }
            }
        } else {
            uint32_t* outP = (uint32_t*)outp;
#pragma unroll
            for (int mb = 0; mb < 4; mb++) {
                int px = xwarp + mb*16 + r4;
#pragma unroll
                for (int nb = 0; nb < 4; nb++) {
                    uint32_t* orow = outP + (size_t)(b*16 + nb*4 + c4)*HW
                                   + (y0 + ywarp)*256 + x0 + px;
                    orow[0] = packh2(acc[mb][nb][0], acc[mb][nb][1]);
                    orow[8] = packh2(acc[mb][nb][2], acc[mb][nb][3]);
                }
            }
        }
        __syncthreads();   // guard smem ring (and s_tg) across pool tiles
    }
}

// ---------------------------------------------------------------------------
extern "C" void kernel_launch(void* const* d_in, const int* in_sizes, int n_in,
                              void* d_out, int out_size)
{
    const float* x     = (const float*)d_in[0];
    const float* w_in  = (const float*)d_in[1];
    const float* w2    = (const float*)d_in[2];
    const float* w3    = (const float*)d_in[3];
    const float* w_out = (const float*)d_in[4];
    const float* i1w   = (const float*)d_in[5];
    const float* i1b   = (const float*)d_in[6];
    const float* i2w   = (const float*)d_in[7];
    const float* i2b   = (const float*)d_in[8];
    float* out = (float*)d_out;

    uint32_t *dXP, *dA, *dB;
    int* dCtr;
    __half *dWin, *dW2, *dW3;
    cudaGetSymbolAddress((void**)&dXP, g_xpk);
    cudaGetSymbolAddress((void**)&dA, g_bufA);
    cudaGetSymbolAddress((void**)&dB, g_bufB);
    cudaGetSymbolAddress((void**)&dCtr, g_ctr);
    cudaGetSymbolAddress((void**)&dWin, g_win_h);
    cudaGetSymbolAddress((void**)&dW2, g_w2_h);
    cudaGetSymbolAddress((void**)&dW3, g_w3_h);

    const int SMEMC = (3*6528 + 3*2304) * 4;   // 105984 B -> 2 CTAs/SM
    cudaFuncSetAttribute((const void*)fused_kernel<16,2,0>,
                         cudaFuncAttributeMaxDynamicSharedMemorySize, SMEMC);
    cudaFuncSetAttribute((const void*)fused_kernel<64,8,0>,
                         cudaFuncAttributeMaxDynamicSharedMemorySize, SMEMC);
    cudaFuncSetAttribute((const void*)fused_kernel<64,8,2>,
                         cudaFuncAttributeMaxDynamicSharedMemorySize, SMEMC);

    // reset conv tile pool counters (graph-capturable)
    cudaMemsetAsync(dCtr, 0, 8*sizeof(int));

    // weight prep + input pack
    prep_w_f16<32> <<<(32*32*9  + 255)/256, 256>>>(w_in, dWin);
    prep_w_f16<128><<<(32*128*9 + 255)/256, 256>>>(w2, dW2);
    prep_w_f16<128><<<(32*128*9 + 255)/256, 256>>>(w3, dW3);
    pack_x_kernel<<<Bn*16*HW/4/256, 256>>>(x, dXP);

    // Software-pipelined halves (h0 = b 0..3 = tiles 0..511, h1 = 512..1023):
    // K1: conv_in(h0)
    fused_kernel<16,2,0><<<296, 256, SMEMC>>>(dXP, (const uint32_t*)dWin, dA,
        nullptr, 0, 512, 0, nullptr, nullptr, nullptr, nullptr, 0, 0);
    // K2: conv_in(h1) || scan1(h0)
    fused_kernel<16,2,0><<<296, 256, SMEMC>>>(dXP, (const uint32_t*)dWin, dA,
        nullptr, 512, 512, 1, dA, dB, i1w, i1b, 0, 256);
    // K3: conv2(h0) || scan1(h1)
    fused_kernel<64,8,0><<<296, 256, SMEMC>>>(dB, (const uint32_t*)dW2, dA,
        nullptr, 0, 512, 2, dA, dB, i1w, i1b, 4, 256);
    // K4: conv2(h1) || scan2(h0)
    fused_kernel<64,8,0><<<296, 256, SMEMC>>>(dB, (const uint32_t*)dW2, dA,
        nullptr, 512, 512, 3, dA, dB, i2w, i2b, 0, 256);
    // K5: conv3+out(h0) || scan2(h1)
    fused_kernel<64,8,2><<<296, 256, SMEMC>>>(dB, (const uint32_t*)dW3, out,
        w_out, 0, 512, 4, dA, dB, i2w, i2b, 4, 256);
    // K6: conv3+out(h1)
    fused_kernel<64,8,2><<<296, 256, SMEMC>>>(dB, (const uint32_t*)dW3, out,
        w_out, 512, 512, 5, nullptr, nullptr, nullptr, nullptr, 0, 0);
}